// round 14
// baseline (speedup 1.0000x reference)
#include <cuda_runtime.h>
#include <cuda_bf16.h>
#include <math.h>
#include <stdint.h>

// Problem shape (fixed by the reference)
#define BB 4
#define SS 2048
#define DD 1024
#define HH 16
#define HDIM 64
#define MROWS (BB * SS)          // 8192
#define KDIM 1024

// ---------------------------------------------------------------------------
// Scratch: device globals (no cudaMalloc allowed)
// ---------------------------------------------------------------------------
__device__ __nv_bfloat16 g_xh[(size_t)MROWS * KDIM];
__device__ __nv_bfloat16 g_xl[(size_t)MROWS * KDIM];
__device__ __nv_bfloat16 g_qh[(size_t)MROWS * DD];
__device__ __nv_bfloat16 g_ql[(size_t)MROWS * DD];
__device__ __nv_bfloat16 g_kh[(size_t)MROWS * DD];
__device__ __nv_bfloat16 g_kl[(size_t)MROWS * DD];
__device__ __nv_bfloat16 g_vh[(size_t)MROWS * DD];
__device__ __nv_bfloat16 g_vl[(size_t)MROWS * DD];
__device__ __nv_bfloat16 g_yh[(size_t)MROWS * KDIM];
__device__ __nv_bfloat16 g_yl[(size_t)MROWS * KDIM];
__device__ __nv_bfloat16 g_wah[(size_t)3 * DD * KDIM];   // W_attn^T hi/lo [N,K]
__device__ __nv_bfloat16 g_wal[(size_t)3 * DD * KDIM];
__device__ __nv_bfloat16 g_wph[(size_t)DD * KDIM];       // W_proj^T hi/lo [N,K]
__device__ __nv_bfloat16 g_wpl[(size_t)DD * KDIM];

// ---------------------------------------------------------------------------
// PTX helpers (base ISA only: cp.async / ldmatrix / mma.sync)
// ---------------------------------------------------------------------------
__device__ __forceinline__ uint32_t smem_u32(const void* p) {
    uint32_t a;
    asm("{ .reg .u64 t; cvta.to.shared.u64 t, %1; cvt.u32.u64 %0, t; }"
        : "=r"(a) : "l"(p));
    return a;
}

#define CP16(smem, gptr) \
    asm volatile("cp.async.cg.shared.global [%0], [%1], 16;" :: "r"(smem), "l"(gptr))
#define CP_COMMIT() asm volatile("cp.async.commit_group;" ::: "memory")
#define CP_WAIT(n)  asm volatile("cp.async.wait_group %0;" :: "n"(n) : "memory")

__device__ __forceinline__ void ldsm4(uint32_t* r, uint32_t addr) {
    asm volatile("ldmatrix.sync.aligned.m8n8.x4.shared.b16 {%0,%1,%2,%3}, [%4];"
                 : "=r"(r[0]), "=r"(r[1]), "=r"(r[2]), "=r"(r[3]) : "r"(addr));
}
__device__ __forceinline__ void ldsm4t(uint32_t* r, uint32_t addr) {
    asm volatile("ldmatrix.sync.aligned.m8n8.x4.trans.shared.b16 {%0,%1,%2,%3}, [%4];"
                 : "=r"(r[0]), "=r"(r[1]), "=r"(r[2]), "=r"(r[3]) : "r"(addr));
}

__device__ __forceinline__ void mma16816(float* c, const uint32_t* a, const uint32_t* b) {
    asm volatile(
        "mma.sync.aligned.m16n8k16.row.col.f32.bf16.bf16.f32 "
        "{%0,%1,%2,%3}, {%4,%5,%6,%7}, {%8,%9}, {%0,%1,%2,%3};"
        : "+f"(c[0]), "+f"(c[1]), "+f"(c[2]), "+f"(c[3])
        : "r"(a[0]), "r"(a[1]), "r"(a[2]), "r"(a[3]), "r"(b[0]), "r"(b[1]));
}

__device__ __forceinline__ uint32_t pack_bf2(float a, float b) {
    __nv_bfloat162 t = __floats2bfloat162_rn(a, b);
    return *(uint32_t*)&t;
}

// ---------------------------------------------------------------------------
// Fused prep: one launch does x hi/lo split AND both weight transpose-splits.
// ---------------------------------------------------------------------------
#define XB (MROWS * KDIM / 4 / 256)   // 8192 blocks for x

__global__ __launch_bounds__(256) void prep_fused(
    const float* __restrict__ x, __nv_bfloat16* __restrict__ xh,
    __nv_bfloat16* __restrict__ xl,
    const float* __restrict__ Wa, __nv_bfloat16* __restrict__ bah,
    __nv_bfloat16* __restrict__ bal,
    const float* __restrict__ Wp, __nv_bfloat16* __restrict__ bph,
    __nv_bfloat16* __restrict__ bpl)
{
    int bz = blockIdx.x;
    if (bz < XB) {
        int i = bz * 256 + threadIdx.x;
        float4 v = ((const float4*)x)[i];
        __nv_bfloat16 h0 = __float2bfloat16(v.x), h1 = __float2bfloat16(v.y);
        __nv_bfloat16 h2 = __float2bfloat16(v.z), h3 = __float2bfloat16(v.w);
        __nv_bfloat162* hp = (__nv_bfloat162*)xh;
        __nv_bfloat162* lp = (__nv_bfloat162*)xl;
        hp[2 * i + 0] = __halves2bfloat162(h0, h1);
        hp[2 * i + 1] = __halves2bfloat162(h2, h3);
        lp[2 * i + 0] = __floats2bfloat162_rn(v.x - __bfloat162float(h0),
                                              v.y - __bfloat162float(h1));
        lp[2 * i + 1] = __floats2bfloat162_rn(v.z - __bfloat162float(h2),
                                              v.w - __bfloat162float(h3));
        return;
    }
    __shared__ float t[32][33];
    int idx = bz - XB;
    int bx = idx & 127;
    int by = idx >> 7;
    const float* W;
    __nv_bfloat16 *bh, *bl;
    int Nd, n0;
    if (bx < 96) { W = Wa; bh = bah; bl = bal; Nd = 3 * DD; n0 = bx * 32; }
    else         { W = Wp; bh = bph; bl = bpl; Nd = DD;     n0 = (bx - 96) * 32; }
    int k0 = by * 32;
    int tx = threadIdx.x & 31, ty = threadIdx.x >> 5;
    for (int r = ty; r < 32; r += 8)
        t[r][tx] = W[(size_t)(k0 + r) * Nd + n0 + tx];
    __syncthreads();
    for (int r = ty; r < 32; r += 8) {
        float v = t[tx][r];
        __nv_bfloat16 h = __float2bfloat16(v);
        bh[(size_t)(n0 + r) * KDIM + k0 + tx] = h;
        bl[(size_t)(n0 + r) * KDIM + k0 + tx] = __float2bfloat16(v - __bfloat162float(h));
    }
}

// ---------------------------------------------------------------------------
// mma.sync bf16x3 GEMM, 2 CTAs/SM (unchanged — best measured)
// ---------------------------------------------------------------------------
#define GBM 128
#define GBN 128
#define GBK 32
#define TILE_BYTES (64 * 128)
#define STAGE_BYTES (4 * TILE_BYTES)
#define NSTAGE 3
#define GEMM_SMEM (NSTAGE * STAGE_BYTES)     // 98304

#define QSCALE (0.125f * 1.4426950408889634f)

__device__ __forceinline__ uint32_t a_addr(uint32_t tb, int m0, int ks, int lane) {
    int row = m0 + (lane & 15);
    int p = row >> 1;
    int chl = ((row & 1) << 2) | (ks << 1) | (lane >> 4);
    return tb + p * 128 + ((chl ^ (p & 7)) << 4);
}
__device__ __forceinline__ uint32_t b_addr(uint32_t tb, int n0, int ks, int lane) {
    int row = n0 + (lane & 7) + ((lane >> 4) << 3);
    int p = row >> 1;
    int chl = ((row & 1) << 2) | (ks << 1) | ((lane >> 3) & 1);
    return tb + p * 128 + ((chl ^ (p & 7)) << 4);
}

__global__ __launch_bounds__(256, 2) void gemm_mma_bf16x3(
    const __nv_bfloat16* __restrict__ Ah, const __nv_bfloat16* __restrict__ Al,
    const __nv_bfloat16* __restrict__ Bh, const __nv_bfloat16* __restrict__ Bl,
    const float* __restrict__ bias, float* __restrict__ C, int Nld, int mode,
    __nv_bfloat16* __restrict__ oqh, __nv_bfloat16* __restrict__ oql,
    __nv_bfloat16* __restrict__ okh, __nv_bfloat16* __restrict__ okl,
    __nv_bfloat16* __restrict__ ovh, __nv_bfloat16* __restrict__ ovl)
{
    extern __shared__ __align__(1024) char smraw[];
    const uint32_t sbase = smem_u32(smraw);
    const int tid = threadIdx.x;
    const int lane = tid & 31;
    const int wid = tid >> 5;
    const int wm = wid & 1;
    const int wn = wid >> 1;
    const int row0 = blockIdx.y * GBM;
    const int col0 = blockIdx.x * GBN;

    const int frow = tid >> 2;
    const int fkc  = tid & 3;
    uint32_t so0, so1;
    {
        int p0 = frow >> 1;
        int c0 = (((frow & 1) << 2) | fkc) ^ (p0 & 7);
        so0 = (uint32_t)(p0 * 128 + c0 * 16);
        int r1 = frow + 64;
        int p1 = r1 >> 1;
        int c1 = (((r1 & 1) << 2) | fkc) ^ (p1 & 7);
        so1 = (uint32_t)(p1 * 128 + c1 * 16);
    }
    const __nv_bfloat16* fs0 = Ah + (size_t)(row0 + frow) * KDIM + fkc * 8;
    const __nv_bfloat16* fs1 = Al + (size_t)(row0 + frow) * KDIM + fkc * 8;
    const __nv_bfloat16* fs2 = Bh + (size_t)(col0 + frow) * KDIM + fkc * 8;
    const __nv_bfloat16* fs3 = Bl + (size_t)(col0 + frow) * KDIM + fkc * 8;
    const size_t rstep = (size_t)64 * KDIM;

    float acc[4][4][4];
#pragma unroll
    for (int mi = 0; mi < 4; mi++)
#pragma unroll
        for (int ni = 0; ni < 4; ni++)
#pragma unroll
            for (int q = 0; q < 4; q++) acc[mi][ni][q] = 0.0f;

    auto fill = [&](int s) {
        uint32_t stg = sbase + s * STAGE_BYTES;
        CP16(stg + so0, fs0);                  CP16(stg + so1, fs0 + rstep);
        CP16(stg + TILE_BYTES + so0, fs1);     CP16(stg + TILE_BYTES + so1, fs1 + rstep);
        CP16(stg + 2 * TILE_BYTES + so0, fs2); CP16(stg + 2 * TILE_BYTES + so1, fs2 + rstep);
        CP16(stg + 3 * TILE_BYTES + so0, fs3); CP16(stg + 3 * TILE_BYTES + so1, fs3 + rstep);
        fs0 += GBK; fs1 += GBK; fs2 += GBK; fs3 += GBK;
        CP_COMMIT();
    };

    fill(0);
    fill(1);

    const int NCH = KDIM / GBK;   // 32
    for (int c = 0; c < NCH; c++) {
        int s = c % 3;
        if (c + 2 < NCH) { CP_WAIT(1); } else { CP_WAIT(0); }
        __syncthreads();
        if (c + 2 < NCH) fill((c + 2) % 3);

        uint32_t st = sbase + s * STAGE_BYTES;
#pragma unroll
        for (int ks = 0; ks < 2; ks++) {
            uint32_t aH[4][4], aL[4][4];
#pragma unroll
            for (int mi = 0; mi < 4; mi++) {
                ldsm4(aH[mi], a_addr(st,              wm * 64 + mi * 16, ks, lane));
                ldsm4(aL[mi], a_addr(st + TILE_BYTES, wm * 64 + mi * 16, ks, lane));
            }
#pragma unroll
            for (int g = 0; g < 2; g++) {
                uint32_t bh[4], bl[4];
                ldsm4(bh, b_addr(st + 2 * TILE_BYTES, wn * 32 + g * 16, ks, lane));
                ldsm4(bl, b_addr(st + 3 * TILE_BYTES, wn * 32 + g * 16, ks, lane));
#pragma unroll
                for (int mi = 0; mi < 4; mi++) {
                    mma16816(acc[mi][2 * g],     aH[mi], &bh[0]);
                    mma16816(acc[mi][2 * g + 1], aH[mi], &bh[2]);
                }
#pragma unroll
                for (int mi = 0; mi < 4; mi++) {
                    mma16816(acc[mi][2 * g],     aH[mi], &bl[0]);
                    mma16816(acc[mi][2 * g + 1], aH[mi], &bl[2]);
                }
#pragma unroll
                for (int mi = 0; mi < 4; mi++) {
                    mma16816(acc[mi][2 * g],     aL[mi], &bh[0]);
                    mma16816(acc[mi][2 * g + 1], aL[mi], &bh[2]);
                }
            }
        }
    }

    const int qr = lane >> 2, qc = lane & 3;
    if (mode == 0) {
#pragma unroll
        for (int mi = 0; mi < 4; mi++)
#pragma unroll
            for (int ni = 0; ni < 4; ni++) {
                int row = row0 + wm * 64 + mi * 16 + qr;
                int col = col0 + wn * 32 + ni * 8 + qc * 2;
                float2 bv = *(const float2*)(bias + col);
                float2 v0, v1;
                v0.x = acc[mi][ni][0] + bv.x;  v0.y = acc[mi][ni][1] + bv.y;
                v1.x = acc[mi][ni][2] + bv.x;  v1.y = acc[mi][ni][3] + bv.y;
                *(float2*)(C + (size_t)row * Nld + col) = v0;
                *(float2*)(C + (size_t)(row + 8) * Nld + col) = v1;
            }
    } else {
        int t = col0 >> 10;
        __nv_bfloat16* oh = (t == 0) ? oqh : (t == 1) ? okh : ovh;
        __nv_bfloat16* ol = (t == 0) ? oql : (t == 1) ? okl : ovl;
        float sc = (t == 0) ? QSCALE : 1.0f;
#pragma unroll
        for (int mi = 0; mi < 4; mi++)
#pragma unroll
            for (int ni = 0; ni < 4; ni++) {
                int row = row0 + wm * 64 + mi * 16 + qr;
                int gcol = col0 + wn * 32 + ni * 8 + qc * 2;
                int lcol = gcol & 1023;
                float2 bv = *(const float2*)(bias + gcol);
                float x0 = (acc[mi][ni][0] + bv.x) * sc;
                float x1 = (acc[mi][ni][1] + bv.y) * sc;
                float x2 = (acc[mi][ni][2] + bv.x) * sc;
                float x3 = (acc[mi][ni][3] + bv.y) * sc;
                __nv_bfloat16 h0 = __float2bfloat16(x0), h1 = __float2bfloat16(x1);
                __nv_bfloat16 h2 = __float2bfloat16(x2), h3 = __float2bfloat16(x3);
                size_t i0 = (size_t)row * DD + lcol;
                size_t i1 = (size_t)(row + 8) * DD + lcol;
                *(__nv_bfloat162*)(oh + i0) = __halves2bfloat162(h0, h1);
                *(__nv_bfloat162*)(oh + i1) = __halves2bfloat162(h2, h3);
                *(__nv_bfloat162*)(ol + i0) = __floats2bfloat162_rn(
                    x0 - __bfloat162float(h0), x1 - __bfloat162float(h1));
                *(__nv_bfloat162*)(ol + i1) = __floats2bfloat162_rn(
                    x2 - __bfloat162float(h2), x3 - __bfloat162float(h3));
            }
    }
}

// ---------------------------------------------------------------------------
// Flash attention, mma.sync bf16x3, causal — m32-per-warp version.
// CTA = 128 threads (4 warps x 32 q rows = 128-row Q tile), KV tile 64 rows,
// double-buffered, 2 CTAs/SM (reg cap 256 so regs ~235 fit w/o spills).
// Each K/V fragment now feeds a 32-row m-pair -> SMEM bytes per MMA halved.
// SMEM: Q hi/lo 2x16KB + 2 KV stages x 32KB = 96KB.
// ---------------------------------------------------------------------------
#define ATT_Q_B 16384                          // 128 rows x 128 B
#define ATT_KV_T 8192                          // 64 rows x 128 B per tensor
#define ATT_KV_STAGE (4 * ATT_KV_T)            // 32 KB
#define ATT_SMEM (2 * ATT_Q_B + 2 * ATT_KV_STAGE)   // 98304

__device__ __forceinline__ uint32_t sw128(uint32_t tb, int row, int chunk) {
    return tb + row * 128 + ((chunk ^ (row & 7)) << 4);
}
__device__ __forceinline__ uint32_t fa_a(uint32_t tb, int m0, int ks, int lane) {
    int row = m0 + (lane & 15);
    return sw128(tb, row, ks * 2 + (lane >> 4));
}
__device__ __forceinline__ uint32_t fa_b(uint32_t tb, int n0, int ks, int lane) {
    int row = n0 + (lane & 7) + ((lane >> 4) << 3);
    return sw128(tb, row, ks * 2 + ((lane >> 3) & 1));
}
__device__ __forceinline__ uint32_t fa_v(uint32_t tb, int kv0, int hd0, int lane) {
    int row = kv0 + (((lane >> 3) & 1) << 3) + (lane & 7);
    return sw128(tb, row, (hd0 >> 3) + (lane >> 4));
}

__global__ __launch_bounds__(128, 2) void flash_attn_mma(
    const __nv_bfloat16* __restrict__ qh, const __nv_bfloat16* __restrict__ ql,
    const __nv_bfloat16* __restrict__ kh, const __nv_bfloat16* __restrict__ kl,
    const __nv_bfloat16* __restrict__ vh, const __nv_bfloat16* __restrict__ vl,
    __nv_bfloat16* __restrict__ yh, __nv_bfloat16* __restrict__ yl)
{
    extern __shared__ __align__(1024) char smraw[];
    const uint32_t sb = smem_u32(smraw);
    // LPT: heaviest q-tiles first
    const int qt = (SS / 128 - 1) - blockIdx.x;
    const int h = blockIdx.y, b = blockIdx.z;
    const int tid = threadIdx.x, lane = tid & 31, w = tid >> 5;   // w in 0..3
    const size_t rowbase = (size_t)(b * SS) + qt * 128;
    const int hoff = h * HDIM;

    const uint32_t sQh = sb, sQl = sb + ATT_Q_B;
    const uint32_t sKV = sb + 2 * ATT_Q_B;

    // one-time Q load (128 rows x 64 cols, hi+lo) — completes with first CP_WAIT
    {
        const __nv_bfloat16* qs[2] = {qh, ql};
        for (int i = tid; i < 2048; i += 128) {
            int t = i >> 10, idx = i & 1023, r = idx >> 3, ch = idx & 7;
            CP16(sw128(t ? sQl : sQh, r, ch),
                 qs[t] + (rowbase + r) * DD + hoff + ch * 8);
        }
        CP_COMMIT();
    }

    const __nv_bfloat16* kvs[4] = {kh, kl, vh, vl};
    // fill one 64-row KV tile (j-th) into stage s
    auto fillkv = [&](int j, int s) {
        uint32_t stg = sKV + s * ATT_KV_STAGE;
        size_t kvrow = (size_t)(b * SS) + (size_t)j * 64;
        for (int i = tid; i < 2048; i += 128) {
            int t = i >> 9, idx = i & 511, r = idx >> 3, ch = idx & 7;
            CP16(sw128(stg + t * ATT_KV_T, r, ch),
                 kvs[t] + (kvrow + r) * DD + hoff + ch * 8);
        }
        CP_COMMIT();
    };

    const int nkt = 2 * qt + 2;    // 64-row KV tiles (>= 2 always)
    fillkv(0, 0);
    fillkv(1, 1);

    float o[16][4];
#pragma unroll
    for (int i = 0; i < 16; i++)
#pragma unroll
        for (int q = 0; q < 4; q++) o[i][q] = 0.0f;
    float mrow[2][2] = {{-1e30f, -1e30f}, {-1e30f, -1e30f}};
    float lrow[2][2] = {{0.0f, 0.0f}, {0.0f, 0.0f}};

    uint32_t aQh[4][2][4];          // cached Q-hi fragments (32 regs)
    const int qr = lane >> 2, qc = lane & 3;

    for (int kt = 0; kt < nkt; kt++) {
        int s = kt & 1;
        if (kt + 1 < nkt) { CP_WAIT(1); } else { CP_WAIT(0); }
        __syncthreads();

        if (kt == 0) {
#pragma unroll
            for (int ks = 0; ks < 4; ks++)
#pragma unroll
                for (int mi = 0; mi < 2; mi++)
                    ldsm4(aQh[ks][mi], fa_a(sQh, w * 32 + mi * 16, ks, lane));
        }

        uint32_t tKh = sKV + s * ATT_KV_STAGE;
        uint32_t tKl = tKh + ATT_KV_T;
        uint32_t tVh = tKh + 2 * ATT_KV_T;
        uint32_t tVl = tKh + 3 * ATT_KV_T;

        // ---- S = Q @ K^T : 32 q rows x 64 kv per warp ----
        float sfr[16][4];            // [mi*8 + n][4]
#pragma unroll
        for (int i = 0; i < 16; i++)
#pragma unroll
            for (int q = 0; q < 4; q++) sfr[i][q] = 0.0f;

#pragma unroll
        for (int ks = 0; ks < 4; ks++) {
            uint32_t qlo[2][4];      // Q-lo reloaded (saves 32 cached regs)
            ldsm4(qlo[0], fa_a(sQl, w * 32,      ks, lane));
            ldsm4(qlo[1], fa_a(sQl, w * 32 + 16, ks, lane));
#pragma unroll
            for (int g = 0; g < 4; g++) {     // 16-kv-col groups
                uint32_t bh4[4], bl4[4];
                ldsm4(bh4, fa_b(tKh, g * 16, ks, lane));
                ldsm4(bl4, fa_b(tKl, g * 16, ks, lane));
#pragma unroll
                for (int mi = 0; mi < 2; mi++) {
                    float* f0 = sfr[mi * 8 + 2 * g];
                    float* f1 = sfr[mi * 8 + 2 * g + 1];
                    mma16816(f0, aQh[ks][mi], &bh4[0]);
                    mma16816(f1, aQh[ks][mi], &bh4[2]);
                    mma16816(f0, aQh[ks][mi], &bl4[0]);
                    mma16816(f1, aQh[ks][mi], &bl4[2]);
                    mma16816(f0, qlo[mi],     &bh4[0]);
                    mma16816(f1, qlo[mi],     &bh4[2]);
                }
            }
        }

        // ---- causal mask (last two KV tiles straddle the diagonal) ----
        if (kt >= 2 * qt) {
            int cbase = kt * 64 - qt * 128;    // 0 or 64
#pragma unroll
            for (int mi = 0; mi < 2; mi++) {
                int r0 = w * 32 + mi * 16 + qr;
#pragma unroll
                for (int n = 0; n < 8; n++) {
                    float* f = sfr[mi * 8 + n];
                    int c0 = cbase + n * 8 + qc * 2;
                    if (c0 > r0)     f[0] = -1e30f;
                    if (c0 + 1 > r0) f[1] = -1e30f;
                    if (c0 > r0 + 8)     f[2] = -1e30f;
                    if (c0 + 1 > r0 + 8) f[3] = -1e30f;
                }
            }
        }

        // ---- online softmax (4 row-sets: mi x {qr, qr+8}) ----
        float al[2][2], rs[2][2];
#pragma unroll
        for (int mi = 0; mi < 2; mi++) {
            float tm0 = -1e30f, tm1 = -1e30f;
#pragma unroll
            for (int n = 0; n < 8; n++) {
                float* f = sfr[mi * 8 + n];
                tm0 = fmaxf(tm0, fmaxf(f[0], f[1]));
                tm1 = fmaxf(tm1, fmaxf(f[2], f[3]));
            }
#pragma unroll
            for (int off = 1; off <= 2; off <<= 1) {
                tm0 = fmaxf(tm0, __shfl_xor_sync(0xffffffffu, tm0, off));
                tm1 = fmaxf(tm1, __shfl_xor_sync(0xffffffffu, tm1, off));
            }
            float mn0 = fmaxf(mrow[mi][0], tm0), mn1 = fmaxf(mrow[mi][1], tm1);
            al[mi][0] = exp2f(mrow[mi][0] - mn0);
            al[mi][1] = exp2f(mrow[mi][1] - mn1);
            mrow[mi][0] = mn0; mrow[mi][1] = mn1;

            float r0 = 0.0f, r1 = 0.0f;
#pragma unroll
            for (int n = 0; n < 8; n++) {
                float* f = sfr[mi * 8 + n];
                f[0] = exp2f(f[0] - mn0);
                f[1] = exp2f(f[1] - mn0);
                f[2] = exp2f(f[2] - mn1);
                f[3] = exp2f(f[3] - mn1);
                r0 += f[0] + f[1];
                r1 += f[2] + f[3];
            }
            rs[mi][0] = r0; rs[mi][1] = r1;
#pragma unroll
            for (int n = 0; n < 8; n++) {
                float* oo = o[mi * 8 + n];
                oo[0] *= al[mi][0]; oo[1] *= al[mi][0];
                oo[2] *= al[mi][1]; oo[3] *= al[mi][1];
            }
        }

        // ---- O += P @ V : V fragments shared across both m-tiles ----
#pragma unroll
        for (int kk = 0; kk < 4; kk++) {       // kv k-groups of 16
            uint32_t phx[2][4], plx[2][4];
#pragma unroll
            for (int mi = 0; mi < 2; mi++) {
                const float* f0 = sfr[mi * 8 + 2 * kk];
                const float* f1 = sfr[mi * 8 + 2 * kk + 1];
                phx[mi][0] = pack_bf2(f0[0], f0[1]);
                phx[mi][1] = pack_bf2(f0[2], f0[3]);
                phx[mi][2] = pack_bf2(f1[0], f1[1]);
                phx[mi][3] = pack_bf2(f1[2], f1[3]);
                __nv_bfloat162 h0 = *(__nv_bfloat162*)&phx[mi][0];
                __nv_bfloat162 h1 = *(__nv_bfloat162*)&phx[mi][1];
                __nv_bfloat162 h2 = *(__nv_bfloat162*)&phx[mi][2];
                __nv_bfloat162 h3 = *(__nv_bfloat162*)&phx[mi][3];
                plx[mi][0] = pack_bf2(f0[0] - __bfloat162float(h0.x), f0[1] - __bfloat162float(h0.y));
                plx[mi][1] = pack_bf2(f0[2] - __bfloat162float(h1.x), f0[3] - __bfloat162float(h1.y));
                plx[mi][2] = pack_bf2(f1[0] - __bfloat162float(h2.x), f1[1] - __bfloat162float(h2.y));
                plx[mi][3] = pack_bf2(f1[2] - __bfloat162float(h3.x), f1[3] - __bfloat162float(h3.y));
            }
#pragma unroll
            for (int gp = 0; gp < 2; gp++) {
                int ng0 = 2 * gp, ng1 = 2 * gp + 1;
                uint32_t vhA[4], vlA[4], vhB[4], vlB[4];
                ldsm4t(vhA, fa_v(tVh, kk * 16, ng0 * 16, lane));
                ldsm4t(vlA, fa_v(tVl, kk * 16, ng0 * 16, lane));
                ldsm4t(vhB, fa_v(tVh, kk * 16, ng1 * 16, lane));
                ldsm4t(vlB, fa_v(tVl, kk * 16, ng1 * 16, lane));
#pragma unroll
                for (int mi = 0; mi < 2; mi++) {
                    float* oA0 = o[mi * 8 + 2 * ng0];
                    float* oA1 = o[mi * 8 + 2 * ng0 + 1];
                    float* oB0 = o[mi * 8 + 2 * ng1];
                    float* oB1 = o[mi * 8 + 2 * ng1 + 1];
                    mma16816(oA0, phx[mi], &vhA[0]);
                    mma16816(oA1, phx[mi], &vhA[2]);
                    mma16816(oB0, phx[mi], &vhB[0]);
                    mma16816(oB1, phx[mi], &vhB[2]);
                    mma16816(oA0, plx[mi], &vhA[0]);
                    mma16816(oA1, plx[mi], &vhA[2]);
                    mma16816(oB0, plx[mi], &vhB[0]);
                    mma16816(oB1, plx[mi], &vhB[2]);
                    mma16816(oA0, phx[mi], &vlA[0]);
                    mma16816(oA1, phx[mi], &vlA[2]);
                    mma16816(oB0, phx[mi], &vlB[0]);
                    mma16816(oB1, phx[mi], &vlB[2]);
                }
            }
        }

        // deferred row-sum reductions (off the tensor critical path)
#pragma unroll
        for (int mi = 0; mi < 2; mi++) {
            float r0 = rs[mi][0], r1 = rs[mi][1];
#pragma unroll
            for (int off = 1; off <= 2; off <<= 1) {
                r0 += __shfl_xor_sync(0xffffffffu, r0, off);
                r1 += __shfl_xor_sync(0xffffffffu, r1, off);
            }
            lrow[mi][0] = lrow[mi][0] * al[mi][0] + r0;
            lrow[mi][1] = lrow[mi][1] * al[mi][1] + r1;
        }

        __syncthreads();   // all warps done reading stage s
        if (kt + 2 < nkt) fillkv(kt + 2, s);
    }

    // ---- epilogue: O/l -> yh/yl ----
#pragma unroll
    for (int mi = 0; mi < 2; mi++) {
        float inv0 = 1.0f / lrow[mi][0];
        float inv1 = 1.0f / lrow[mi][1];
        size_t r0 = rowbase + w * 32 + mi * 16 + qr;
#pragma unroll
        for (int i = 0; i < 8; i++) {
            int col = hoff + i * 8 + qc * 2;
            const float* oo = o[mi * 8 + i];
            float x0 = oo[0] * inv0, x1 = oo[1] * inv0;
            float x2 = oo[2] * inv1, x3 = oo[3] * inv1;
            __nv_bfloat16 h0 = __float2bfloat16(x0), h1 = __float2bfloat16(x1);
            __nv_bfloat16 h2 = __float2bfloat16(x2), h3 = __float2bfloat16(x3);
            size_t i0 = r0 * DD + col;
            size_t i1 = (r0 + 8) * DD + col;
            *(__nv_bfloat162*)(yh + i0) = __halves2bfloat162(h0, h1);
            *(__nv_bfloat162*)(yh + i1) = __halves2bfloat162(h2, h3);
            *(__nv_bfloat162*)(yl + i0) = __floats2bfloat162_rn(
                x0 - __bfloat162float(h0), x1 - __bfloat162float(h1));
            *(__nv_bfloat162*)(yl + i1) = __floats2bfloat162_rn(
                x2 - __bfloat162float(h2), x3 - __bfloat162float(h3));
        }
    }
}

// ---------------------------------------------------------------------------
extern "C" void kernel_launch(void* const* d_in, const int* in_sizes, int n_in,
                              void* d_out, int out_size)
{
    const float* x      = (const float*)d_in[0];
    const float* W_attn = (const float*)d_in[1];
    const float* b_attn = (const float*)d_in[2];
    const float* W_proj = (const float*)d_in[3];
    const float* b_proj = (const float*)d_in[4];
    float* out = (float*)d_out;

    __nv_bfloat16 *xh, *xl, *qhp, *qlp, *khp, *klp, *vhp, *vlp, *yhp, *ylp;
    __nv_bfloat16 *wah, *wal, *wph, *wpl;
    cudaGetSymbolAddress((void**)&xh,  g_xh);
    cudaGetSymbolAddress((void**)&xl,  g_xl);
    cudaGetSymbolAddress((void**)&qhp, g_qh);
    cudaGetSymbolAddress((void**)&qlp, g_ql);
    cudaGetSymbolAddress((void**)&khp, g_kh);
    cudaGetSymbolAddress((void**)&klp, g_kl);
    cudaGetSymbolAddress((void**)&vhp, g_vh);
    cudaGetSymbolAddress((void**)&vlp, g_vl);
    cudaGetSymbolAddress((void**)&yhp, g_yh);
    cudaGetSymbolAddress((void**)&ylp, g_yl);
    cudaGetSymbolAddress((void**)&wah, g_wah);
    cudaGetSymbolAddress((void**)&wal, g_wal);
    cudaGetSymbolAddress((void**)&wph, g_wph);
    cudaGetSymbolAddress((void**)&wpl, g_wpl);

    cudaFuncSetAttribute(gemm_mma_bf16x3, cudaFuncAttributeMaxDynamicSharedMemorySize,
                         (int)GEMM_SMEM);
    cudaFuncSetAttribute(flash_attn_mma, cudaFuncAttributeMaxDynamicSharedMemorySize,
                         (int)ATT_SMEM);

    prep_fused<<<XB + 4096, 256>>>(x, xh, xl, W_attn, wah, wal, W_proj, wph, wpl);

    gemm_mma_bf16x3<<<dim3(3 * DD / GBN, MROWS / GBM), 256, GEMM_SMEM>>>(
        xh, xl, wah, wal, b_attn, nullptr, 3 * DD, 1,
        qhp, qlp, khp, klp, vhp, vlp);

    flash_attn_mma<<<dim3(SS / 128, HH, BB), 128, ATT_SMEM>>>(
        qhp, qlp, khp, klp, vhp, vlp, yhp, ylp);

    gemm_mma_bf16x3<<<dim3(DD / GBN, MROWS / GBM), 256, GEMM_SMEM>>>(
        yhp, ylp, wph, wpl, b_proj, out, DD, 0,
        nullptr, nullptr, nullptr, nullptr, nullptr, nullptr);
}

// round 15
// speedup vs baseline: 1.0269x; 1.0269x over previous
#include <cuda_runtime.h>
#include <cuda_bf16.h>
#include <math.h>
#include <stdint.h>

// Problem shape (fixed by the reference)
#define BB 4
#define SS 2048
#define DD 1024
#define HH 16
#define HDIM 64
#define MROWS (BB * SS)          // 8192
#define KDIM 1024

// ---------------------------------------------------------------------------
// Scratch: device globals (no cudaMalloc allowed)
// ---------------------------------------------------------------------------
__device__ __nv_bfloat16 g_xh[(size_t)MROWS * KDIM];
__device__ __nv_bfloat16 g_xl[(size_t)MROWS * KDIM];
__device__ __nv_bfloat16 g_qh[(size_t)MROWS * DD];
__device__ __nv_bfloat16 g_ql[(size_t)MROWS * DD];
__device__ __nv_bfloat16 g_kh[(size_t)MROWS * DD];
__device__ __nv_bfloat16 g_kl[(size_t)MROWS * DD];
__device__ __nv_bfloat16 g_vh[(size_t)MROWS * DD];
__device__ __nv_bfloat16 g_vl[(size_t)MROWS * DD];
__device__ __nv_bfloat16 g_yh[(size_t)MROWS * KDIM];
__device__ __nv_bfloat16 g_yl[(size_t)MROWS * KDIM];
__device__ __nv_bfloat16 g_wah[(size_t)3 * DD * KDIM];   // W_attn^T hi/lo [N,K]
__device__ __nv_bfloat16 g_wal[(size_t)3 * DD * KDIM];
__device__ __nv_bfloat16 g_wph[(size_t)DD * KDIM];       // W_proj^T hi/lo [N,K]
__device__ __nv_bfloat16 g_wpl[(size_t)DD * KDIM];

// ---------------------------------------------------------------------------
// PTX helpers (base ISA only: cp.async / ldmatrix / mma.sync)
// ---------------------------------------------------------------------------
__device__ __forceinline__ uint32_t smem_u32(const void* p) {
    uint32_t a;
    asm("{ .reg .u64 t; cvta.to.shared.u64 t, %1; cvt.u32.u64 %0, t; }"
        : "=r"(a) : "l"(p));
    return a;
}

#define CP16(smem, gptr) \
    asm volatile("cp.async.cg.shared.global [%0], [%1], 16;" :: "r"(smem), "l"(gptr))
#define CP_COMMIT() asm volatile("cp.async.commit_group;" ::: "memory")
#define CP_WAIT(n)  asm volatile("cp.async.wait_group %0;" :: "n"(n) : "memory")

__device__ __forceinline__ void ldsm4(uint32_t* r, uint32_t addr) {
    asm volatile("ldmatrix.sync.aligned.m8n8.x4.shared.b16 {%0,%1,%2,%3}, [%4];"
                 : "=r"(r[0]), "=r"(r[1]), "=r"(r[2]), "=r"(r[3]) : "r"(addr));
}
__device__ __forceinline__ void ldsm4t(uint32_t* r, uint32_t addr) {
    asm volatile("ldmatrix.sync.aligned.m8n8.x4.trans.shared.b16 {%0,%1,%2,%3}, [%4];"
                 : "=r"(r[0]), "=r"(r[1]), "=r"(r[2]), "=r"(r[3]) : "r"(addr));
}

__device__ __forceinline__ void mma16816(float* c, const uint32_t* a, const uint32_t* b) {
    asm volatile(
        "mma.sync.aligned.m16n8k16.row.col.f32.bf16.bf16.f32 "
        "{%0,%1,%2,%3}, {%4,%5,%6,%7}, {%8,%9}, {%0,%1,%2,%3};"
        : "+f"(c[0]), "+f"(c[1]), "+f"(c[2]), "+f"(c[3])
        : "r"(a[0]), "r"(a[1]), "r"(a[2]), "r"(a[3]), "r"(b[0]), "r"(b[1]));
}

__device__ __forceinline__ uint32_t pack_bf2(float a, float b) {
    __nv_bfloat162 t = __floats2bfloat162_rn(a, b);
    return *(uint32_t*)&t;
}

// ---------------------------------------------------------------------------
// Fused prep: one launch does x hi/lo split AND both weight transpose-splits.
// ---------------------------------------------------------------------------
#define XB (MROWS * KDIM / 4 / 256)   // 8192 blocks for x

__global__ __launch_bounds__(256) void prep_fused(
    const float* __restrict__ x, __nv_bfloat16* __restrict__ xh,
    __nv_bfloat16* __restrict__ xl,
    const float* __restrict__ Wa, __nv_bfloat16* __restrict__ bah,
    __nv_bfloat16* __restrict__ bal,
    const float* __restrict__ Wp, __nv_bfloat16* __restrict__ bph,
    __nv_bfloat16* __restrict__ bpl)
{
    int bz = blockIdx.x;
    if (bz < XB) {
        int i = bz * 256 + threadIdx.x;
        float4 v = ((const float4*)x)[i];
        __nv_bfloat16 h0 = __float2bfloat16(v.x), h1 = __float2bfloat16(v.y);
        __nv_bfloat16 h2 = __float2bfloat16(v.z), h3 = __float2bfloat16(v.w);
        __nv_bfloat162* hp = (__nv_bfloat162*)xh;
        __nv_bfloat162* lp = (__nv_bfloat162*)xl;
        hp[2 * i + 0] = __halves2bfloat162(h0, h1);
        hp[2 * i + 1] = __halves2bfloat162(h2, h3);
        lp[2 * i + 0] = __floats2bfloat162_rn(v.x - __bfloat162float(h0),
                                              v.y - __bfloat162float(h1));
        lp[2 * i + 1] = __floats2bfloat162_rn(v.z - __bfloat162float(h2),
                                              v.w - __bfloat162float(h3));
        return;
    }
    __shared__ float t[32][33];
    int idx = bz - XB;
    int bx = idx & 127;
    int by = idx >> 7;
    const float* W;
    __nv_bfloat16 *bh, *bl;
    int Nd, n0;
    if (bx < 96) { W = Wa; bh = bah; bl = bal; Nd = 3 * DD; n0 = bx * 32; }
    else         { W = Wp; bh = bph; bl = bpl; Nd = DD;     n0 = (bx - 96) * 32; }
    int k0 = by * 32;
    int tx = threadIdx.x & 31, ty = threadIdx.x >> 5;
    for (int r = ty; r < 32; r += 8)
        t[r][tx] = W[(size_t)(k0 + r) * Nd + n0 + tx];
    __syncthreads();
    for (int r = ty; r < 32; r += 8) {
        float v = t[tx][r];
        __nv_bfloat16 h = __float2bfloat16(v);
        bh[(size_t)(n0 + r) * KDIM + k0 + tx] = h;
        bl[(size_t)(n0 + r) * KDIM + k0 + tx] = __float2bfloat16(v - __bfloat162float(h));
    }
}

// ---------------------------------------------------------------------------
// mma.sync bf16x3 GEMM, 2 CTAs/SM (unchanged — best measured)
// ---------------------------------------------------------------------------
#define GBM 128
#define GBN 128
#define GBK 32
#define TILE_BYTES (64 * 128)
#define STAGE_BYTES (4 * TILE_BYTES)
#define NSTAGE 3
#define GEMM_SMEM (NSTAGE * STAGE_BYTES)     // 98304

#define QSCALE (0.125f * 1.4426950408889634f)

__device__ __forceinline__ uint32_t a_addr(uint32_t tb, int m0, int ks, int lane) {
    int row = m0 + (lane & 15);
    int p = row >> 1;
    int chl = ((row & 1) << 2) | (ks << 1) | (lane >> 4);
    return tb + p * 128 + ((chl ^ (p & 7)) << 4);
}
__device__ __forceinline__ uint32_t b_addr(uint32_t tb, int n0, int ks, int lane) {
    int row = n0 + (lane & 7) + ((lane >> 4) << 3);
    int p = row >> 1;
    int chl = ((row & 1) << 2) | (ks << 1) | ((lane >> 3) & 1);
    return tb + p * 128 + ((chl ^ (p & 7)) << 4);
}

__global__ __launch_bounds__(256, 2) void gemm_mma_bf16x3(
    const __nv_bfloat16* __restrict__ Ah, const __nv_bfloat16* __restrict__ Al,
    const __nv_bfloat16* __restrict__ Bh, const __nv_bfloat16* __restrict__ Bl,
    const float* __restrict__ bias, float* __restrict__ C, int Nld, int mode,
    __nv_bfloat16* __restrict__ oqh, __nv_bfloat16* __restrict__ oql,
    __nv_bfloat16* __restrict__ okh, __nv_bfloat16* __restrict__ okl,
    __nv_bfloat16* __restrict__ ovh, __nv_bfloat16* __restrict__ ovl)
{
    extern __shared__ __align__(1024) char smraw[];
    const uint32_t sbase = smem_u32(smraw);
    const int tid = threadIdx.x;
    const int lane = tid & 31;
    const int wid = tid >> 5;
    const int wm = wid & 1;
    const int wn = wid >> 1;
    const int row0 = blockIdx.y * GBM;
    const int col0 = blockIdx.x * GBN;

    const int frow = tid >> 2;
    const int fkc  = tid & 3;
    uint32_t so0, so1;
    {
        int p0 = frow >> 1;
        int c0 = (((frow & 1) << 2) | fkc) ^ (p0 & 7);
        so0 = (uint32_t)(p0 * 128 + c0 * 16);
        int r1 = frow + 64;
        int p1 = r1 >> 1;
        int c1 = (((r1 & 1) << 2) | fkc) ^ (p1 & 7);
        so1 = (uint32_t)(p1 * 128 + c1 * 16);
    }
    const __nv_bfloat16* fs0 = Ah + (size_t)(row0 + frow) * KDIM + fkc * 8;
    const __nv_bfloat16* fs1 = Al + (size_t)(row0 + frow) * KDIM + fkc * 8;
    const __nv_bfloat16* fs2 = Bh + (size_t)(col0 + frow) * KDIM + fkc * 8;
    const __nv_bfloat16* fs3 = Bl + (size_t)(col0 + frow) * KDIM + fkc * 8;
    const size_t rstep = (size_t)64 * KDIM;

    float acc[4][4][4];
#pragma unroll
    for (int mi = 0; mi < 4; mi++)
#pragma unroll
        for (int ni = 0; ni < 4; ni++)
#pragma unroll
            for (int q = 0; q < 4; q++) acc[mi][ni][q] = 0.0f;

    auto fill = [&](int s) {
        uint32_t stg = sbase + s * STAGE_BYTES;
        CP16(stg + so0, fs0);                  CP16(stg + so1, fs0 + rstep);
        CP16(stg + TILE_BYTES + so0, fs1);     CP16(stg + TILE_BYTES + so1, fs1 + rstep);
        CP16(stg + 2 * TILE_BYTES + so0, fs2); CP16(stg + 2 * TILE_BYTES + so1, fs2 + rstep);
        CP16(stg + 3 * TILE_BYTES + so0, fs3); CP16(stg + 3 * TILE_BYTES + so1, fs3 + rstep);
        fs0 += GBK; fs1 += GBK; fs2 += GBK; fs3 += GBK;
        CP_COMMIT();
    };

    fill(0);
    fill(1);

    const int NCH = KDIM / GBK;   // 32
    for (int c = 0; c < NCH; c++) {
        int s = c % 3;
        if (c + 2 < NCH) { CP_WAIT(1); } else { CP_WAIT(0); }
        __syncthreads();
        if (c + 2 < NCH) fill((c + 2) % 3);

        uint32_t st = sbase + s * STAGE_BYTES;
#pragma unroll
        for (int ks = 0; ks < 2; ks++) {
            uint32_t aH[4][4], aL[4][4];
#pragma unroll
            for (int mi = 0; mi < 4; mi++) {
                ldsm4(aH[mi], a_addr(st,              wm * 64 + mi * 16, ks, lane));
                ldsm4(aL[mi], a_addr(st + TILE_BYTES, wm * 64 + mi * 16, ks, lane));
            }
#pragma unroll
            for (int g = 0; g < 2; g++) {
                uint32_t bh[4], bl[4];
                ldsm4(bh, b_addr(st + 2 * TILE_BYTES, wn * 32 + g * 16, ks, lane));
                ldsm4(bl, b_addr(st + 3 * TILE_BYTES, wn * 32 + g * 16, ks, lane));
#pragma unroll
                for (int mi = 0; mi < 4; mi++) {
                    mma16816(acc[mi][2 * g],     aH[mi], &bh[0]);
                    mma16816(acc[mi][2 * g + 1], aH[mi], &bh[2]);
                }
#pragma unroll
                for (int mi = 0; mi < 4; mi++) {
                    mma16816(acc[mi][2 * g],     aH[mi], &bl[0]);
                    mma16816(acc[mi][2 * g + 1], aH[mi], &bl[2]);
                }
#pragma unroll
                for (int mi = 0; mi < 4; mi++) {
                    mma16816(acc[mi][2 * g],     aL[mi], &bh[0]);
                    mma16816(acc[mi][2 * g + 1], aL[mi], &bh[2]);
                }
            }
        }
    }

    const int qr = lane >> 2, qc = lane & 3;
    if (mode == 0) {
#pragma unroll
        for (int mi = 0; mi < 4; mi++)
#pragma unroll
            for (int ni = 0; ni < 4; ni++) {
                int row = row0 + wm * 64 + mi * 16 + qr;
                int col = col0 + wn * 32 + ni * 8 + qc * 2;
                float2 bv = *(const float2*)(bias + col);
                float2 v0, v1;
                v0.x = acc[mi][ni][0] + bv.x;  v0.y = acc[mi][ni][1] + bv.y;
                v1.x = acc[mi][ni][2] + bv.x;  v1.y = acc[mi][ni][3] + bv.y;
                *(float2*)(C + (size_t)row * Nld + col) = v0;
                *(float2*)(C + (size_t)(row + 8) * Nld + col) = v1;
            }
    } else {
        int t = col0 >> 10;
        __nv_bfloat16* oh = (t == 0) ? oqh : (t == 1) ? okh : ovh;
        __nv_bfloat16* ol = (t == 0) ? oql : (t == 1) ? okl : ovl;
        float sc = (t == 0) ? QSCALE : 1.0f;
#pragma unroll
        for (int mi = 0; mi < 4; mi++)
#pragma unroll
            for (int ni = 0; ni < 4; ni++) {
                int row = row0 + wm * 64 + mi * 16 + qr;
                int gcol = col0 + wn * 32 + ni * 8 + qc * 2;
                int lcol = gcol & 1023;
                float2 bv = *(const float2*)(bias + gcol);
                float x0 = (acc[mi][ni][0] + bv.x) * sc;
                float x1 = (acc[mi][ni][1] + bv.y) * sc;
                float x2 = (acc[mi][ni][2] + bv.x) * sc;
                float x3 = (acc[mi][ni][3] + bv.y) * sc;
                __nv_bfloat16 h0 = __float2bfloat16(x0), h1 = __float2bfloat16(x1);
                __nv_bfloat16 h2 = __float2bfloat16(x2), h3 = __float2bfloat16(x3);
                size_t i0 = (size_t)row * DD + lcol;
                size_t i1 = (size_t)(row + 8) * DD + lcol;
                *(__nv_bfloat162*)(oh + i0) = __halves2bfloat162(h0, h1);
                *(__nv_bfloat162*)(oh + i1) = __halves2bfloat162(h2, h3);
                *(__nv_bfloat162*)(ol + i0) = __floats2bfloat162_rn(
                    x0 - __bfloat162float(h0), x1 - __bfloat162float(h1));
                *(__nv_bfloat162*)(ol + i1) = __floats2bfloat162_rn(
                    x2 - __bfloat162float(h2), x3 - __bfloat162float(h3));
            }
    }
}

// ---------------------------------------------------------------------------
// Flash attention, mma.sync bf16x3, causal — R13 structure (128-thread CTAs,
// 64-row Q tile, 128-row KV single-buffered, 2 CTAs/SM, LPT ordering) with
// SPLIT K/V cp.async groups: V's load latency is hidden behind the S-phase
// MMAs and softmax instead of being serialized before them.
// ---------------------------------------------------------------------------
#define ATT_Q_B 8192                           // 64 rows x 128 B
#define ATT_KV_T 16384                         // 128 rows x 128 B per tensor
#define ATT_SMEM (2 * ATT_Q_B + 4 * ATT_KV_T)  // 81920

__device__ __forceinline__ uint32_t sw128(uint32_t tb, int row, int chunk) {
    return tb + row * 128 + ((chunk ^ (row & 7)) << 4);
}
__device__ __forceinline__ uint32_t fa_a(uint32_t tb, int m0, int ks, int lane) {
    int row = m0 + (lane & 15);
    return sw128(tb, row, ks * 2 + (lane >> 4));
}
__device__ __forceinline__ uint32_t fa_b(uint32_t tb, int n0, int ks, int lane) {
    int row = n0 + (lane & 7) + ((lane >> 4) << 3);
    return sw128(tb, row, ks * 2 + ((lane >> 3) & 1));
}
__device__ __forceinline__ uint32_t fa_v(uint32_t tb, int kv0, int hd0, int lane) {
    int row = kv0 + (((lane >> 3) & 1) << 3) + (lane & 7);
    return sw128(tb, row, (hd0 >> 3) + (lane >> 4));
}

__global__ __launch_bounds__(128, 2) void flash_attn_mma(
    const __nv_bfloat16* __restrict__ qh, const __nv_bfloat16* __restrict__ ql,
    const __nv_bfloat16* __restrict__ kh, const __nv_bfloat16* __restrict__ kl,
    const __nv_bfloat16* __restrict__ vh, const __nv_bfloat16* __restrict__ vl,
    __nv_bfloat16* __restrict__ yh, __nv_bfloat16* __restrict__ yl)
{
    extern __shared__ __align__(1024) char smraw[];
    const uint32_t sb = smem_u32(smraw);
    // LPT: heaviest q-tiles first
    const int qt = (SS / 64 - 1) - blockIdx.x;
    const int h = blockIdx.y, b = blockIdx.z;
    const int tid = threadIdx.x, lane = tid & 31, w = tid >> 5;   // w in 0..3
    const size_t rowbase = (size_t)(b * SS) + qt * 64;
    const int hoff = h * HDIM;

    const uint32_t sQh = sb, sQl = sb + ATT_Q_B;
    const uint32_t tKh = sb + 2 * ATT_Q_B;
    const uint32_t tKl = tKh + ATT_KV_T;
    const uint32_t tVh = tKh + 2 * ATT_KV_T;
    const uint32_t tVl = tKh + 3 * ATT_KV_T;

    // one-time Q load (group committed before first K group)
    {
        const __nv_bfloat16* qs[2] = {qh, ql};
        for (int i = tid; i < 1024; i += 128) {
            int t = i >> 9, idx = i & 511, r = idx >> 3, ch = idx & 7;
            CP16(sw128(t ? sQl : sQh, r, ch),
                 qs[t] + (rowbase + r) * DD + hoff + ch * 8);
        }
        CP_COMMIT();
    }

    const __nv_bfloat16* kvs[4] = {kh, kl, vh, vl};
    // K tiles (hi+lo) as one commit group; V tiles as a second group
    auto fillK = [&](int kt) {
        size_t kvrow = (size_t)(b * SS) + (size_t)kt * 128;
        for (int i = tid; i < 2048; i += 128) {
            int t = i >> 10, idx = i & 1023, r = idx >> 3, ch = idx & 7;
            CP16(sw128(tKh + t * ATT_KV_T, r, ch),
                 kvs[t] + (kvrow + r) * DD + hoff + ch * 8);
        }
        CP_COMMIT();
    };
    auto fillV = [&](int kt) {
        size_t kvrow = (size_t)(b * SS) + (size_t)kt * 128;
        for (int i = tid; i < 2048; i += 128) {
            int t = i >> 10, idx = i & 1023, r = idx >> 3, ch = idx & 7;
            CP16(sw128(tVh + t * ATT_KV_T, r, ch),
                 kvs[2 + t] + (kvrow + r) * DD + hoff + ch * 8);
        }
        CP_COMMIT();
    };

    float o[8][4];
#pragma unroll
    for (int i = 0; i < 8; i++)
#pragma unroll
        for (int q = 0; q < 4; q++) o[i][q] = 0.0f;
    float mrow[2] = {-1e30f, -1e30f};
    float lrow[2] = {0.0f, 0.0f};

    uint32_t aQh[4][4], aQl[4][4];
    const int qr = lane >> 2, qc = lane & 3;

    const int nkt = (qt + 2) >> 1;   // ceil((qt+1)*64 / 128)

    for (int kt = 0; kt < nkt; kt++) {
        fillK(kt);
        fillV(kt);
        CP_WAIT(1);        // Q + K landed; V group may still be in flight
        __syncthreads();

        if (kt == 0) {
#pragma unroll
            for (int ks = 0; ks < 4; ks++) {
                ldsm4(aQh[ks], fa_a(sQh, w * 16, ks, lane));
                ldsm4(aQl[ks], fa_a(sQl, w * 16, ks, lane));
            }
        }

        // ---- S = Q @ K^T (V load overlaps this entire phase) ----
        float sfr[16][4];
#pragma unroll
        for (int i = 0; i < 16; i++)
#pragma unroll
            for (int q = 0; q < 4; q++) sfr[i][q] = 0.0f;

#pragma unroll
        for (int ks = 0; ks < 4; ks++)
#pragma unroll
            for (int np = 0; np < 4; np++) {
                int ng0 = 2 * np, ng1 = 2 * np + 1;
                uint32_t bhA[4], blA[4], bhB[4], blB[4];
                ldsm4(bhA, fa_b(tKh, ng0 * 16, ks, lane));
                ldsm4(blA, fa_b(tKl, ng0 * 16, ks, lane));
                ldsm4(bhB, fa_b(tKh, ng1 * 16, ks, lane));
                ldsm4(blB, fa_b(tKl, ng1 * 16, ks, lane));
                mma16816(sfr[2 * ng0],     aQh[ks], &bhA[0]);
                mma16816(sfr[2 * ng0 + 1], aQh[ks], &bhA[2]);
                mma16816(sfr[2 * ng1],     aQh[ks], &bhB[0]);
                mma16816(sfr[2 * ng1 + 1], aQh[ks], &bhB[2]);
                mma16816(sfr[2 * ng0],     aQh[ks], &blA[0]);
                mma16816(sfr[2 * ng0 + 1], aQh[ks], &blA[2]);
                mma16816(sfr[2 * ng1],     aQh[ks], &blB[0]);
                mma16816(sfr[2 * ng1 + 1], aQh[ks], &blB[2]);
                mma16816(sfr[2 * ng0],     aQl[ks], &bhA[0]);
                mma16816(sfr[2 * ng0 + 1], aQl[ks], &bhA[2]);
                mma16816(sfr[2 * ng1],     aQl[ks], &bhB[0]);
                mma16816(sfr[2 * ng1 + 1], aQl[ks], &bhB[2]);
            }

        // ---- causal mask (only the last KV tile overlaps the diagonal) ----
        if (kt == nkt - 1) {
            int r0 = w * 16 + qr;
            int cbase = kt * 128 - qt * 64;
#pragma unroll
            for (int nf = 0; nf < 16; nf++) {
                int c0 = cbase + nf * 8 + qc * 2;
                if (c0 > r0)     sfr[nf][0] = -1e30f;
                if (c0 + 1 > r0) sfr[nf][1] = -1e30f;
                if (c0 > r0 + 8)     sfr[nf][2] = -1e30f;
                if (c0 + 1 > r0 + 8) sfr[nf][3] = -1e30f;
            }
        }

        // ---- online softmax ----
        float tm0 = -1e30f, tm1 = -1e30f;
#pragma unroll
        for (int nf = 0; nf < 16; nf++) {
            tm0 = fmaxf(tm0, fmaxf(sfr[nf][0], sfr[nf][1]));
            tm1 = fmaxf(tm1, fmaxf(sfr[nf][2], sfr[nf][3]));
        }
#pragma unroll
        for (int off = 1; off <= 2; off <<= 1) {
            tm0 = fmaxf(tm0, __shfl_xor_sync(0xffffffffu, tm0, off));
            tm1 = fmaxf(tm1, __shfl_xor_sync(0xffffffffu, tm1, off));
        }
        float mn0 = fmaxf(mrow[0], tm0), mn1 = fmaxf(mrow[1], tm1);
        float al0 = exp2f(mrow[0] - mn0), al1 = exp2f(mrow[1] - mn1);
        mrow[0] = mn0; mrow[1] = mn1;
#pragma unroll
        for (int i = 0; i < 8; i++) {
            o[i][0] *= al0; o[i][1] *= al0;
            o[i][2] *= al1; o[i][3] *= al1;
        }

        float rs0 = 0.0f, rs1 = 0.0f;
#pragma unroll
        for (int nf = 0; nf < 16; nf++) {
            sfr[nf][0] = exp2f(sfr[nf][0] - mn0);
            sfr[nf][1] = exp2f(sfr[nf][1] - mn0);
            sfr[nf][2] = exp2f(sfr[nf][2] - mn1);
            sfr[nf][3] = exp2f(sfr[nf][3] - mn1);
            rs0 += sfr[nf][0] + sfr[nf][1];
            rs1 += sfr[nf][2] + sfr[nf][3];
        }

        CP_WAIT(0);        // V landed
        __syncthreads();

        // ---- O += P @ V ----
#pragma unroll
        for (int ks = 0; ks < 8; ks++) {
            const float* f0 = sfr[2 * ks];
            const float* f1 = sfr[2 * ks + 1];
            uint32_t phx[4], plx[4];
            phx[0] = pack_bf2(f0[0], f0[1]);
            phx[1] = pack_bf2(f0[2], f0[3]);
            phx[2] = pack_bf2(f1[0], f1[1]);
            phx[3] = pack_bf2(f1[2], f1[3]);
            {
                __nv_bfloat162 h0 = *(__nv_bfloat162*)&phx[0];
                __nv_bfloat162 h1 = *(__nv_bfloat162*)&phx[1];
                __nv_bfloat162 h2 = *(__nv_bfloat162*)&phx[2];
                __nv_bfloat162 h3 = *(__nv_bfloat162*)&phx[3];
                plx[0] = pack_bf2(f0[0] - __bfloat162float(h0.x), f0[1] - __bfloat162float(h0.y));
                plx[1] = pack_bf2(f0[2] - __bfloat162float(h1.x), f0[3] - __bfloat162float(h1.y));
                plx[2] = pack_bf2(f1[0] - __bfloat162float(h2.x), f1[1] - __bfloat162float(h2.y));
                plx[3] = pack_bf2(f1[2] - __bfloat162float(h3.x), f1[3] - __bfloat162float(h3.y));
            }
#pragma unroll
            for (int gp = 0; gp < 2; gp++) {
                int ng0 = 2 * gp, ng1 = 2 * gp + 1;
                uint32_t vhA[4], vlA[4], vhB[4], vlB[4];
                ldsm4t(vhA, fa_v(tVh, ks * 16, ng0 * 16, lane));
                ldsm4t(vlA, fa_v(tVl, ks * 16, ng0 * 16, lane));
                ldsm4t(vhB, fa_v(tVh, ks * 16, ng1 * 16, lane));
                ldsm4t(vlB, fa_v(tVl, ks * 16, ng1 * 16, lane));
                mma16816(o[2 * ng0],     phx, &vhA[0]);
                mma16816(o[2 * ng0 + 1], phx, &vhA[2]);
                mma16816(o[2 * ng1],     phx, &vhB[0]);
                mma16816(o[2 * ng1 + 1], phx, &vhB[2]);
                mma16816(o[2 * ng0],     plx, &vhA[0]);
                mma16816(o[2 * ng0 + 1], plx, &vhA[2]);
                mma16816(o[2 * ng1],     plx, &vhB[0]);
                mma16816(o[2 * ng1 + 1], plx, &vhB[2]);
                mma16816(o[2 * ng0],     phx, &vlA[0]);
                mma16816(o[2 * ng0 + 1], phx, &vlA[2]);
                mma16816(o[2 * ng1],     phx, &vlB[0]);
                mma16816(o[2 * ng1 + 1], phx, &vlB[2]);
            }
        }

        // deferred row-sum reduction (off the tensor critical path)
#pragma unroll
        for (int off = 1; off <= 2; off <<= 1) {
            rs0 += __shfl_xor_sync(0xffffffffu, rs0, off);
            rs1 += __shfl_xor_sync(0xffffffffu, rs1, off);
        }
        lrow[0] = lrow[0] * al0 + rs0;
        lrow[1] = lrow[1] * al1 + rs1;

        __syncthreads();   // all warps done reading KV before next overwrite
    }

    // ---- epilogue: O/l -> yh/yl ----
    float inv0 = 1.0f / lrow[0];
    float inv1 = 1.0f / lrow[1];
    size_t r0 = rowbase + w * 16 + qr;
#pragma unroll
    for (int i = 0; i < 8; i++) {
        int col = hoff + i * 8 + qc * 2;
        float x0 = o[i][0] * inv0, x1 = o[i][1] * inv0;
        float x2 = o[i][2] * inv1, x3 = o[i][3] * inv1;
        __nv_bfloat16 h0 = __float2bfloat16(x0), h1 = __float2bfloat16(x1);
        __nv_bfloat16 h2 = __float2bfloat16(x2), h3 = __float2bfloat16(x3);
        size_t i0 = r0 * DD + col;
        size_t i1 = (r0 + 8) * DD + col;
        *(__nv_bfloat162*)(yh + i0) = __halves2bfloat162(h0, h1);
        *(__nv_bfloat162*)(yh + i1) = __halves2bfloat162(h2, h3);
        *(__nv_bfloat162*)(yl + i0) = __floats2bfloat162_rn(
            x0 - __bfloat162float(h0), x1 - __bfloat162float(h1));
        *(__nv_bfloat162*)(yl + i1) = __floats2bfloat162_rn(
            x2 - __bfloat162float(h2), x3 - __bfloat162float(h3));
    }
}

// ---------------------------------------------------------------------------
extern "C" void kernel_launch(void* const* d_in, const int* in_sizes, int n_in,
                              void* d_out, int out_size)
{
    const float* x      = (const float*)d_in[0];
    const float* W_attn = (const float*)d_in[1];
    const float* b_attn = (const float*)d_in[2];
    const float* W_proj = (const float*)d_in[3];
    const float* b_proj = (const float*)d_in[4];
    float* out = (float*)d_out;

    __nv_bfloat16 *xh, *xl, *qhp, *qlp, *khp, *klp, *vhp, *vlp, *yhp, *ylp;
    __nv_bfloat16 *wah, *wal, *wph, *wpl;
    cudaGetSymbolAddress((void**)&xh,  g_xh);
    cudaGetSymbolAddress((void**)&xl,  g_xl);
    cudaGetSymbolAddress((void**)&qhp, g_qh);
    cudaGetSymbolAddress((void**)&qlp, g_ql);
    cudaGetSymbolAddress((void**)&khp, g_kh);
    cudaGetSymbolAddress((void**)&klp, g_kl);
    cudaGetSymbolAddress((void**)&vhp, g_vh);
    cudaGetSymbolAddress((void**)&vlp, g_vl);
    cudaGetSymbolAddress((void**)&yhp, g_yh);
    cudaGetSymbolAddress((void**)&ylp, g_yl);
    cudaGetSymbolAddress((void**)&wah, g_wah);
    cudaGetSymbolAddress((void**)&wal, g_wal);
    cudaGetSymbolAddress((void**)&wph, g_wph);
    cudaGetSymbolAddress((void**)&wpl, g_wpl);

    cudaFuncSetAttribute(gemm_mma_bf16x3, cudaFuncAttributeMaxDynamicSharedMemorySize,
                         (int)GEMM_SMEM);
    cudaFuncSetAttribute(flash_attn_mma, cudaFuncAttributeMaxDynamicSharedMemorySize,
                         (int)ATT_SMEM);

    prep_fused<<<XB + 4096, 256>>>(x, xh, xl, W_attn, wah, wal, W_proj, wph, wpl);

    gemm_mma_bf16x3<<<dim3(3 * DD / GBN, MROWS / GBM), 256, GEMM_SMEM>>>(
        xh, xl, wah, wal, b_attn, nullptr, 3 * DD, 1,
        qhp, qlp, khp, klp, vhp, vlp);

    flash_attn_mma<<<dim3(SS / 64, HH, BB), 128, ATT_SMEM>>>(
        qhp, qlp, khp, klp, vhp, vlp, yhp, ylp);

    gemm_mma_bf16x3<<<dim3(DD / GBN, MROWS / GBM), 256, GEMM_SMEM>>>(
        yhp, ylp, wph, wpl, b_proj, out, DD, 0,
        nullptr, nullptr, nullptr, nullptr, nullptr, nullptr);
}

// round 16
// speedup vs baseline: 1.0867x; 1.0583x over previous
#include <cuda_runtime.h>
#include <cuda_bf16.h>
#include <cuda_fp16.h>
#include <math.h>
#include <stdint.h>

// Problem shape (fixed by the reference)
#define BB 4
#define SS 2048
#define DD 1024
#define HH 16
#define HDIM 64
#define MROWS (BB * SS)          // 8192
#define KDIM 1024

// ---------------------------------------------------------------------------
// Scratch: device globals (no cudaMalloc allowed)
// g_vh/g_vl hold fp16 (V path); others bf16.
// ---------------------------------------------------------------------------
__device__ __nv_bfloat16 g_xh[(size_t)MROWS * KDIM];
__device__ __nv_bfloat16 g_xl[(size_t)MROWS * KDIM];
__device__ __nv_bfloat16 g_qh[(size_t)MROWS * DD];
__device__ __nv_bfloat16 g_ql[(size_t)MROWS * DD];
__device__ __nv_bfloat16 g_kh[(size_t)MROWS * DD];
__device__ __nv_bfloat16 g_kl[(size_t)MROWS * DD];
__device__ __half        g_vh[(size_t)MROWS * DD];
__device__ __half        g_vl[(size_t)MROWS * DD];
__device__ __nv_bfloat16 g_yh[(size_t)MROWS * KDIM];
__device__ __nv_bfloat16 g_yl[(size_t)MROWS * KDIM];
__device__ __nv_bfloat16 g_wah[(size_t)3 * DD * KDIM];   // W_attn^T hi/lo [N,K]
__device__ __nv_bfloat16 g_wal[(size_t)3 * DD * KDIM];
__device__ __nv_bfloat16 g_wph[(size_t)DD * KDIM];       // W_proj^T hi/lo [N,K]
__device__ __nv_bfloat16 g_wpl[(size_t)DD * KDIM];

// ---------------------------------------------------------------------------
// PTX helpers (base ISA only: cp.async / ldmatrix / mma.sync)
// ---------------------------------------------------------------------------
__device__ __forceinline__ uint32_t smem_u32(const void* p) {
    uint32_t a;
    asm("{ .reg .u64 t; cvta.to.shared.u64 t, %1; cvt.u32.u64 %0, t; }"
        : "=r"(a) : "l"(p));
    return a;
}

#define CP16(smem, gptr) \
    asm volatile("cp.async.cg.shared.global [%0], [%1], 16;" :: "r"(smem), "l"(gptr))
#define CP_COMMIT() asm volatile("cp.async.commit_group;" ::: "memory")
#define CP_WAIT(n)  asm volatile("cp.async.wait_group %0;" :: "n"(n) : "memory")

__device__ __forceinline__ void ldsm4(uint32_t* r, uint32_t addr) {
    asm volatile("ldmatrix.sync.aligned.m8n8.x4.shared.b16 {%0,%1,%2,%3}, [%4];"
                 : "=r"(r[0]), "=r"(r[1]), "=r"(r[2]), "=r"(r[3]) : "r"(addr));
}
__device__ __forceinline__ void ldsm4t(uint32_t* r, uint32_t addr) {
    asm volatile("ldmatrix.sync.aligned.m8n8.x4.trans.shared.b16 {%0,%1,%2,%3}, [%4];"
                 : "=r"(r[0]), "=r"(r[1]), "=r"(r[2]), "=r"(r[3]) : "r"(addr));
}

// bf16 mma
__device__ __forceinline__ void mma16816(float* c, const uint32_t* a, const uint32_t* b) {
    asm volatile(
        "mma.sync.aligned.m16n8k16.row.col.f32.bf16.bf16.f32 "
        "{%0,%1,%2,%3}, {%4,%5,%6,%7}, {%8,%9}, {%0,%1,%2,%3};"
        : "+f"(c[0]), "+f"(c[1]), "+f"(c[2]), "+f"(c[3])
        : "r"(a[0]), "r"(a[1]), "r"(a[2]), "r"(a[3]), "r"(b[0]), "r"(b[1]));
}
// fp16 mma (for P @ V)
__device__ __forceinline__ void mma16816h(float* c, const uint32_t* a, const uint32_t* b) {
    asm volatile(
        "mma.sync.aligned.m16n8k16.row.col.f32.f16.f16.f32 "
        "{%0,%1,%2,%3}, {%4,%5,%6,%7}, {%8,%9}, {%0,%1,%2,%3};"
        : "+f"(c[0]), "+f"(c[1]), "+f"(c[2]), "+f"(c[3])
        : "r"(a[0]), "r"(a[1]), "r"(a[2]), "r"(a[3]), "r"(b[0]), "r"(b[1]));
}

__device__ __forceinline__ uint32_t pack_h2(float a, float b) {
    __half2 t = __floats2half2_rn(a, b);
    return *(uint32_t*)&t;
}

// ---------------------------------------------------------------------------
// Fused prep: one launch does x hi/lo split AND both weight transpose-splits.
// ---------------------------------------------------------------------------
#define XB (MROWS * KDIM / 4 / 256)   // 8192 blocks for x

__global__ __launch_bounds__(256) void prep_fused(
    const float* __restrict__ x, __nv_bfloat16* __restrict__ xh,
    __nv_bfloat16* __restrict__ xl,
    const float* __restrict__ Wa, __nv_bfloat16* __restrict__ bah,
    __nv_bfloat16* __restrict__ bal,
    const float* __restrict__ Wp, __nv_bfloat16* __restrict__ bph,
    __nv_bfloat16* __restrict__ bpl)
{
    int bz = blockIdx.x;
    if (bz < XB) {
        int i = bz * 256 + threadIdx.x;
        float4 v = ((const float4*)x)[i];
        __nv_bfloat16 h0 = __float2bfloat16(v.x), h1 = __float2bfloat16(v.y);
        __nv_bfloat16 h2 = __float2bfloat16(v.z), h3 = __float2bfloat16(v.w);
        __nv_bfloat162* hp = (__nv_bfloat162*)xh;
        __nv_bfloat162* lp = (__nv_bfloat162*)xl;
        hp[2 * i + 0] = __halves2bfloat162(h0, h1);
        hp[2 * i + 1] = __halves2bfloat162(h2, h3);
        lp[2 * i + 0] = __floats2bfloat162_rn(v.x - __bfloat162float(h0),
                                              v.y - __bfloat162float(h1));
        lp[2 * i + 1] = __floats2bfloat162_rn(v.z - __bfloat162float(h2),
                                              v.w - __bfloat162float(h3));
        return;
    }
    __shared__ float t[32][33];
    int idx = bz - XB;
    int bx = idx & 127;
    int by = idx >> 7;
    const float* W;
    __nv_bfloat16 *bh, *bl;
    int Nd, n0;
    if (bx < 96) { W = Wa; bh = bah; bl = bal; Nd = 3 * DD; n0 = bx * 32; }
    else         { W = Wp; bh = bph; bl = bpl; Nd = DD;     n0 = (bx - 96) * 32; }
    int k0 = by * 32;
    int tx = threadIdx.x & 31, ty = threadIdx.x >> 5;
    for (int r = ty; r < 32; r += 8)
        t[r][tx] = W[(size_t)(k0 + r) * Nd + n0 + tx];
    __syncthreads();
    for (int r = ty; r < 32; r += 8) {
        float v = t[tx][r];
        __nv_bfloat16 h = __float2bfloat16(v);
        bh[(size_t)(n0 + r) * KDIM + k0 + tx] = h;
        bl[(size_t)(n0 + r) * KDIM + k0 + tx] = __float2bfloat16(v - __bfloat162float(h));
    }
}

// ---------------------------------------------------------------------------
// mma.sync bf16x3 GEMM, 2 CTAs/SM.
//   mode 0: fp32 epilogue; mode 1: split-write q/k (bf16) and v (fp16).
// ---------------------------------------------------------------------------
#define GBM 128
#define GBN 128
#define GBK 32
#define TILE_BYTES (64 * 128)
#define STAGE_BYTES (4 * TILE_BYTES)
#define NSTAGE 3
#define GEMM_SMEM (NSTAGE * STAGE_BYTES)     // 98304

#define QSCALE (0.125f * 1.4426950408889634f)

__device__ __forceinline__ uint32_t a_addr(uint32_t tb, int m0, int ks, int lane) {
    int row = m0 + (lane & 15);
    int p = row >> 1;
    int chl = ((row & 1) << 2) | (ks << 1) | (lane >> 4);
    return tb + p * 128 + ((chl ^ (p & 7)) << 4);
}
__device__ __forceinline__ uint32_t b_addr(uint32_t tb, int n0, int ks, int lane) {
    int row = n0 + (lane & 7) + ((lane >> 4) << 3);
    int p = row >> 1;
    int chl = ((row & 1) << 2) | (ks << 1) | ((lane >> 3) & 1);
    return tb + p * 128 + ((chl ^ (p & 7)) << 4);
}

__global__ __launch_bounds__(256, 2) void gemm_mma_bf16x3(
    const __nv_bfloat16* __restrict__ Ah, const __nv_bfloat16* __restrict__ Al,
    const __nv_bfloat16* __restrict__ Bh, const __nv_bfloat16* __restrict__ Bl,
    const float* __restrict__ bias, float* __restrict__ C, int Nld, int mode,
    __nv_bfloat16* __restrict__ oqh, __nv_bfloat16* __restrict__ oql,
    __nv_bfloat16* __restrict__ okh, __nv_bfloat16* __restrict__ okl,
    __half* __restrict__ ovh, __half* __restrict__ ovl)
{
    extern __shared__ __align__(1024) char smraw[];
    const uint32_t sbase = smem_u32(smraw);
    const int tid = threadIdx.x;
    const int lane = tid & 31;
    const int wid = tid >> 5;
    const int wm = wid & 1;
    const int wn = wid >> 1;
    const int row0 = blockIdx.y * GBM;
    const int col0 = blockIdx.x * GBN;

    const int frow = tid >> 2;
    const int fkc  = tid & 3;
    uint32_t so0, so1;
    {
        int p0 = frow >> 1;
        int c0 = (((frow & 1) << 2) | fkc) ^ (p0 & 7);
        so0 = (uint32_t)(p0 * 128 + c0 * 16);
        int r1 = frow + 64;
        int p1 = r1 >> 1;
        int c1 = (((r1 & 1) << 2) | fkc) ^ (p1 & 7);
        so1 = (uint32_t)(p1 * 128 + c1 * 16);
    }
    const __nv_bfloat16* fs0 = Ah + (size_t)(row0 + frow) * KDIM + fkc * 8;
    const __nv_bfloat16* fs1 = Al + (size_t)(row0 + frow) * KDIM + fkc * 8;
    const __nv_bfloat16* fs2 = Bh + (size_t)(col0 + frow) * KDIM + fkc * 8;
    const __nv_bfloat16* fs3 = Bl + (size_t)(col0 + frow) * KDIM + fkc * 8;
    const size_t rstep = (size_t)64 * KDIM;

    float acc[4][4][4];
#pragma unroll
    for (int mi = 0; mi < 4; mi++)
#pragma unroll
        for (int ni = 0; ni < 4; ni++)
#pragma unroll
            for (int q = 0; q < 4; q++) acc[mi][ni][q] = 0.0f;

    auto fill = [&](int s) {
        uint32_t stg = sbase + s * STAGE_BYTES;
        CP16(stg + so0, fs0);                  CP16(stg + so1, fs0 + rstep);
        CP16(stg + TILE_BYTES + so0, fs1);     CP16(stg + TILE_BYTES + so1, fs1 + rstep);
        CP16(stg + 2 * TILE_BYTES + so0, fs2); CP16(stg + 2 * TILE_BYTES + so1, fs2 + rstep);
        CP16(stg + 3 * TILE_BYTES + so0, fs3); CP16(stg + 3 * TILE_BYTES + so1, fs3 + rstep);
        fs0 += GBK; fs1 += GBK; fs2 += GBK; fs3 += GBK;
        CP_COMMIT();
    };

    fill(0);
    fill(1);

    const int NCH = KDIM / GBK;   // 32
    for (int c = 0; c < NCH; c++) {
        int s = c % 3;
        if (c + 2 < NCH) { CP_WAIT(1); } else { CP_WAIT(0); }
        __syncthreads();
        if (c + 2 < NCH) fill((c + 2) % 3);

        uint32_t st = sbase + s * STAGE_BYTES;
#pragma unroll
        for (int ks = 0; ks < 2; ks++) {
            uint32_t aH[4][4], aL[4][4];
#pragma unroll
            for (int mi = 0; mi < 4; mi++) {
                ldsm4(aH[mi], a_addr(st,              wm * 64 + mi * 16, ks, lane));
                ldsm4(aL[mi], a_addr(st + TILE_BYTES, wm * 64 + mi * 16, ks, lane));
            }
#pragma unroll
            for (int g = 0; g < 2; g++) {
                uint32_t bh[4], bl[4];
                ldsm4(bh, b_addr(st + 2 * TILE_BYTES, wn * 32 + g * 16, ks, lane));
                ldsm4(bl, b_addr(st + 3 * TILE_BYTES, wn * 32 + g * 16, ks, lane));
#pragma unroll
                for (int mi = 0; mi < 4; mi++) {
                    mma16816(acc[mi][2 * g],     aH[mi], &bh[0]);
                    mma16816(acc[mi][2 * g + 1], aH[mi], &bh[2]);
                }
#pragma unroll
                for (int mi = 0; mi < 4; mi++) {
                    mma16816(acc[mi][2 * g],     aH[mi], &bl[0]);
                    mma16816(acc[mi][2 * g + 1], aH[mi], &bl[2]);
                }
#pragma unroll
                for (int mi = 0; mi < 4; mi++) {
                    mma16816(acc[mi][2 * g],     aL[mi], &bh[0]);
                    mma16816(acc[mi][2 * g + 1], aL[mi], &bh[2]);
                }
            }
        }
    }

    const int qr = lane >> 2, qc = lane & 3;
    if (mode == 0) {
#pragma unroll
        for (int mi = 0; mi < 4; mi++)
#pragma unroll
            for (int ni = 0; ni < 4; ni++) {
                int row = row0 + wm * 64 + mi * 16 + qr;
                int col = col0 + wn * 32 + ni * 8 + qc * 2;
                float2 bv = *(const float2*)(bias + col);
                float2 v0, v1;
                v0.x = acc[mi][ni][0] + bv.x;  v0.y = acc[mi][ni][1] + bv.y;
                v1.x = acc[mi][ni][2] + bv.x;  v1.y = acc[mi][ni][3] + bv.y;
                *(float2*)(C + (size_t)row * Nld + col) = v0;
                *(float2*)(C + (size_t)(row + 8) * Nld + col) = v1;
            }
    } else {
        int t = col0 >> 10;   // 0=q, 1=k, 2=v
        if (t == 2) {
            // V: fp16 hi/lo split
#pragma unroll
            for (int mi = 0; mi < 4; mi++)
#pragma unroll
                for (int ni = 0; ni < 4; ni++) {
                    int row = row0 + wm * 64 + mi * 16 + qr;
                    int gcol = col0 + wn * 32 + ni * 8 + qc * 2;
                    int lcol = gcol & 1023;
                    float2 bv = *(const float2*)(bias + gcol);
                    float x0 = acc[mi][ni][0] + bv.x;
                    float x1 = acc[mi][ni][1] + bv.y;
                    float x2 = acc[mi][ni][2] + bv.x;
                    float x3 = acc[mi][ni][3] + bv.y;
                    __half h0 = __float2half_rn(x0), h1 = __float2half_rn(x1);
                    __half h2 = __float2half_rn(x2), h3 = __float2half_rn(x3);
                    size_t i0 = (size_t)row * DD + lcol;
                    size_t i1 = (size_t)(row + 8) * DD + lcol;
                    *(__half2*)(ovh + i0) = __halves2half2(h0, h1);
                    *(__half2*)(ovh + i1) = __halves2half2(h2, h3);
                    *(__half2*)(ovl + i0) = __floats2half2_rn(
                        x0 - __half2float(h0), x1 - __half2float(h1));
                    *(__half2*)(ovl + i1) = __floats2half2_rn(
                        x2 - __half2float(h2), x3 - __half2float(h3));
                }
        } else {
            __nv_bfloat16* oh = (t == 0) ? oqh : okh;
            __nv_bfloat16* ol = (t == 0) ? oql : okl;
            float sc = (t == 0) ? QSCALE : 1.0f;
#pragma unroll
            for (int mi = 0; mi < 4; mi++)
#pragma unroll
                for (int ni = 0; ni < 4; ni++) {
                    int row = row0 + wm * 64 + mi * 16 + qr;
                    int gcol = col0 + wn * 32 + ni * 8 + qc * 2;
                    int lcol = gcol & 1023;
                    float2 bv = *(const float2*)(bias + gcol);
                    float x0 = (acc[mi][ni][0] + bv.x) * sc;
                    float x1 = (acc[mi][ni][1] + bv.y) * sc;
                    float x2 = (acc[mi][ni][2] + bv.x) * sc;
                    float x3 = (acc[mi][ni][3] + bv.y) * sc;
                    __nv_bfloat16 h0 = __float2bfloat16(x0), h1 = __float2bfloat16(x1);
                    __nv_bfloat16 h2 = __float2bfloat16(x2), h3 = __float2bfloat16(x3);
                    size_t i0 = (size_t)row * DD + lcol;
                    size_t i1 = (size_t)(row + 8) * DD + lcol;
                    *(__nv_bfloat162*)(oh + i0) = __halves2bfloat162(h0, h1);
                    *(__nv_bfloat162*)(oh + i1) = __halves2bfloat162(h2, h3);
                    *(__nv_bfloat162*)(ol + i0) = __floats2bfloat162_rn(
                        x0 - __bfloat162float(h0), x1 - __bfloat162float(h1));
                    *(__nv_bfloat162*)(ol + i1) = __floats2bfloat162_rn(
                        x2 - __bfloat162float(h2), x3 - __bfloat162float(h3));
                }
        }
    }
}

// ---------------------------------------------------------------------------
// Flash attention — R15 structure (split K/V waits) with fp16-P PV:
// P quantized to fp16 (rel err 2^-12), V stored fp16 hi+lo, so PV needs only
// 2 MMAs per V fragment (P*Vh + P*Vl) and no residual P pack.
// ---------------------------------------------------------------------------
#define ATT_Q_B 8192                           // 64 rows x 128 B
#define ATT_KV_T 16384                         // 128 rows x 128 B per tensor
#define ATT_SMEM (2 * ATT_Q_B + 4 * ATT_KV_T)  // 81920

__device__ __forceinline__ uint32_t sw128(uint32_t tb, int row, int chunk) {
    return tb + row * 128 + ((chunk ^ (row & 7)) << 4);
}
__device__ __forceinline__ uint32_t fa_a(uint32_t tb, int m0, int ks, int lane) {
    int row = m0 + (lane & 15);
    return sw128(tb, row, ks * 2 + (lane >> 4));
}
__device__ __forceinline__ uint32_t fa_b(uint32_t tb, int n0, int ks, int lane) {
    int row = n0 + (lane & 7) + ((lane >> 4) << 3);
    return sw128(tb, row, ks * 2 + ((lane >> 3) & 1));
}
__device__ __forceinline__ uint32_t fa_v(uint32_t tb, int kv0, int hd0, int lane) {
    int row = kv0 + (((lane >> 3) & 1) << 3) + (lane & 7);
    return sw128(tb, row, (hd0 >> 3) + (lane >> 4));
}

__global__ __launch_bounds__(128, 2) void flash_attn_mma(
    const __nv_bfloat16* __restrict__ qh, const __nv_bfloat16* __restrict__ ql,
    const __nv_bfloat16* __restrict__ kh, const __nv_bfloat16* __restrict__ kl,
    const __half* __restrict__ vh, const __half* __restrict__ vl,
    __nv_bfloat16* __restrict__ yh, __nv_bfloat16* __restrict__ yl)
{
    extern __shared__ __align__(1024) char smraw[];
    const uint32_t sb = smem_u32(smraw);
    // LPT: heaviest q-tiles first
    const int qt = (SS / 64 - 1) - blockIdx.x;
    const int h = blockIdx.y, b = blockIdx.z;
    const int tid = threadIdx.x, lane = tid & 31, w = tid >> 5;   // w in 0..3
    const size_t rowbase = (size_t)(b * SS) + qt * 64;
    const int hoff = h * HDIM;

    const uint32_t sQh = sb, sQl = sb + ATT_Q_B;
    const uint32_t tKh = sb + 2 * ATT_Q_B;
    const uint32_t tKl = tKh + ATT_KV_T;
    const uint32_t tVh = tKh + 2 * ATT_KV_T;
    const uint32_t tVl = tKh + 3 * ATT_KV_T;

    // one-time Q load (group committed before first K group)
    {
        const __nv_bfloat16* qs[2] = {qh, ql};
        for (int i = tid; i < 1024; i += 128) {
            int t = i >> 9, idx = i & 511, r = idx >> 3, ch = idx & 7;
            CP16(sw128(t ? sQl : sQh, r, ch),
                 qs[t] + (rowbase + r) * DD + hoff + ch * 8);
        }
        CP_COMMIT();
    }

    const __nv_bfloat16* ks2[2] = {kh, kl};
    const __half* vs2[2] = {vh, vl};
    auto fillK = [&](int kt) {
        size_t kvrow = (size_t)(b * SS) + (size_t)kt * 128;
        for (int i = tid; i < 2048; i += 128) {
            int t = i >> 10, idx = i & 1023, r = idx >> 3, ch = idx & 7;
            CP16(sw128(tKh + t * ATT_KV_T, r, ch),
                 ks2[t] + (kvrow + r) * DD + hoff + ch * 8);
        }
        CP_COMMIT();
    };
    auto fillV = [&](int kt) {
        size_t kvrow = (size_t)(b * SS) + (size_t)kt * 128;
        for (int i = tid; i < 2048; i += 128) {
            int t = i >> 10, idx = i & 1023, r = idx >> 3, ch = idx & 7;
            CP16(sw128(tVh + t * ATT_KV_T, r, ch),
                 vs2[t] + (kvrow + r) * DD + hoff + ch * 8);
        }
        CP_COMMIT();
    };

    float o[8][4];
#pragma unroll
    for (int i = 0; i < 8; i++)
#pragma unroll
        for (int q = 0; q < 4; q++) o[i][q] = 0.0f;
    float mrow[2] = {-1e30f, -1e30f};
    float lrow[2] = {0.0f, 0.0f};

    uint32_t aQh[4][4], aQl[4][4];
    const int qr = lane >> 2, qc = lane & 3;

    const int nkt = (qt + 2) >> 1;   // ceil((qt+1)*64 / 128)

    for (int kt = 0; kt < nkt; kt++) {
        fillK(kt);
        fillV(kt);
        CP_WAIT(1);        // Q + K landed; V group may still be in flight
        __syncthreads();

        if (kt == 0) {
#pragma unroll
            for (int ks = 0; ks < 4; ks++) {
                ldsm4(aQh[ks], fa_a(sQh, w * 16, ks, lane));
                ldsm4(aQl[ks], fa_a(sQl, w * 16, ks, lane));
            }
        }

        // ---- S = Q @ K^T (V load overlaps this entire phase) ----
        float sfr[16][4];
#pragma unroll
        for (int i = 0; i < 16; i++)
#pragma unroll
            for (int q = 0; q < 4; q++) sfr[i][q] = 0.0f;

#pragma unroll
        for (int ks = 0; ks < 4; ks++)
#pragma unroll
            for (int np = 0; np < 4; np++) {
                int ng0 = 2 * np, ng1 = 2 * np + 1;
                uint32_t bhA[4], blA[4], bhB[4], blB[4];
                ldsm4(bhA, fa_b(tKh, ng0 * 16, ks, lane));
                ldsm4(blA, fa_b(tKl, ng0 * 16, ks, lane));
                ldsm4(bhB, fa_b(tKh, ng1 * 16, ks, lane));
                ldsm4(blB, fa_b(tKl, ng1 * 16, ks, lane));
                mma16816(sfr[2 * ng0],     aQh[ks], &bhA[0]);
                mma16816(sfr[2 * ng0 + 1], aQh[ks], &bhA[2]);
                mma16816(sfr[2 * ng1],     aQh[ks], &bhB[0]);
                mma16816(sfr[2 * ng1 + 1], aQh[ks], &bhB[2]);
                mma16816(sfr[2 * ng0],     aQh[ks], &blA[0]);
                mma16816(sfr[2 * ng0 + 1], aQh[ks], &blA[2]);
                mma16816(sfr[2 * ng1],     aQh[ks], &blB[0]);
                mma16816(sfr[2 * ng1 + 1], aQh[ks], &blB[2]);
                mma16816(sfr[2 * ng0],     aQl[ks], &bhA[0]);
                mma16816(sfr[2 * ng0 + 1], aQl[ks], &bhA[2]);
                mma16816(sfr[2 * ng1],     aQl[ks], &bhB[0]);
                mma16816(sfr[2 * ng1 + 1], aQl[ks], &bhB[2]);
            }

        // ---- causal mask (only the last KV tile overlaps the diagonal) ----
        if (kt == nkt - 1) {
            int r0 = w * 16 + qr;
            int cbase = kt * 128 - qt * 64;
#pragma unroll
            for (int nf = 0; nf < 16; nf++) {
                int c0 = cbase + nf * 8 + qc * 2;
                if (c0 > r0)     sfr[nf][0] = -1e30f;
                if (c0 + 1 > r0) sfr[nf][1] = -1e30f;
                if (c0 > r0 + 8)     sfr[nf][2] = -1e30f;
                if (c0 + 1 > r0 + 8) sfr[nf][3] = -1e30f;
            }
        }

        // ---- online softmax ----
        float tm0 = -1e30f, tm1 = -1e30f;
#pragma unroll
        for (int nf = 0; nf < 16; nf++) {
            tm0 = fmaxf(tm0, fmaxf(sfr[nf][0], sfr[nf][1]));
            tm1 = fmaxf(tm1, fmaxf(sfr[nf][2], sfr[nf][3]));
        }
#pragma unroll
        for (int off = 1; off <= 2; off <<= 1) {
            tm0 = fmaxf(tm0, __shfl_xor_sync(0xffffffffu, tm0, off));
            tm1 = fmaxf(tm1, __shfl_xor_sync(0xffffffffu, tm1, off));
        }
        float mn0 = fmaxf(mrow[0], tm0), mn1 = fmaxf(mrow[1], tm1);
        float al0 = exp2f(mrow[0] - mn0), al1 = exp2f(mrow[1] - mn1);
        mrow[0] = mn0; mrow[1] = mn1;
#pragma unroll
        for (int i = 0; i < 8; i++) {
            o[i][0] *= al0; o[i][1] *= al0;
            o[i][2] *= al1; o[i][3] *= al1;
        }

        float rs0 = 0.0f, rs1 = 0.0f;
#pragma unroll
        for (int nf = 0; nf < 16; nf++) {
            sfr[nf][0] = exp2f(sfr[nf][0] - mn0);
            sfr[nf][1] = exp2f(sfr[nf][1] - mn0);
            sfr[nf][2] = exp2f(sfr[nf][2] - mn1);
            sfr[nf][3] = exp2f(sfr[nf][3] - mn1);
            rs0 += sfr[nf][0] + sfr[nf][1];
            rs1 += sfr[nf][2] + sfr[nf][3];
        }

        CP_WAIT(0);        // V landed
        __syncthreads();

        // ---- O += P @ V  (P fp16; 2 MMAs per V fragment, no residual pack) ----
#pragma unroll
        for (int ks = 0; ks < 8; ks++) {
            const float* f0 = sfr[2 * ks];
            const float* f1 = sfr[2 * ks + 1];
            uint32_t phx[4];
            phx[0] = pack_h2(f0[0], f0[1]);
            phx[1] = pack_h2(f0[2], f0[3]);
            phx[2] = pack_h2(f1[0], f1[1]);
            phx[3] = pack_h2(f1[2], f1[3]);
#pragma unroll
            for (int gp = 0; gp < 2; gp++) {
                int ng0 = 2 * gp, ng1 = 2 * gp + 1;
                uint32_t vhA[4], vlA[4], vhB[4], vlB[4];
                ldsm4t(vhA, fa_v(tVh, ks * 16, ng0 * 16, lane));
                ldsm4t(vlA, fa_v(tVl, ks * 16, ng0 * 16, lane));
                ldsm4t(vhB, fa_v(tVh, ks * 16, ng1 * 16, lane));
                ldsm4t(vlB, fa_v(tVl, ks * 16, ng1 * 16, lane));
                mma16816h(o[2 * ng0],     phx, &vhA[0]);
                mma16816h(o[2 * ng0 + 1], phx, &vhA[2]);
                mma16816h(o[2 * ng1],     phx, &vhB[0]);
                mma16816h(o[2 * ng1 + 1], phx, &vhB[2]);
                mma16816h(o[2 * ng0],     phx, &vlA[0]);
                mma16816h(o[2 * ng0 + 1], phx, &vlA[2]);
                mma16816h(o[2 * ng1],     phx, &vlB[0]);
                mma16816h(o[2 * ng1 + 1], phx, &vlB[2]);
            }
        }

        // deferred row-sum reduction (off the tensor critical path)
#pragma unroll
        for (int off = 1; off <= 2; off <<= 1) {
            rs0 += __shfl_xor_sync(0xffffffffu, rs0, off);
            rs1 += __shfl_xor_sync(0xffffffffu, rs1, off);
        }
        lrow[0] = lrow[0] * al0 + rs0;
        lrow[1] = lrow[1] * al1 + rs1;

        __syncthreads();   // all warps done reading KV before next overwrite
    }

    // ---- epilogue: O/l -> yh/yl ----
    float inv0 = 1.0f / lrow[0];
    float inv1 = 1.0f / lrow[1];
    size_t r0 = rowbase + w * 16 + qr;
#pragma unroll
    for (int i = 0; i < 8; i++) {
        int col = hoff + i * 8 + qc * 2;
        float x0 = o[i][0] * inv0, x1 = o[i][1] * inv0;
        float x2 = o[i][2] * inv1, x3 = o[i][3] * inv1;
        __nv_bfloat16 h0 = __float2bfloat16(x0), h1 = __float2bfloat16(x1);
        __nv_bfloat16 h2 = __float2bfloat16(x2), h3 = __float2bfloat16(x3);
        size_t i0 = r0 * DD + col;
        size_t i1 = (r0 + 8) * DD + col;
        *(__nv_bfloat162*)(yh + i0) = __halves2bfloat162(h0, h1);
        *(__nv_bfloat162*)(yh + i1) = __halves2bfloat162(h2, h3);
        *(__nv_bfloat162*)(yl + i0) = __floats2bfloat162_rn(
            x0 - __bfloat162float(h0), x1 - __bfloat162float(h1));
        *(__nv_bfloat162*)(yl + i1) = __floats2bfloat162_rn(
            x2 - __bfloat162float(h2), x3 - __bfloat162float(h3));
    }
}

// ---------------------------------------------------------------------------
extern "C" void kernel_launch(void* const* d_in, const int* in_sizes, int n_in,
                              void* d_out, int out_size)
{
    const float* x      = (const float*)d_in[0];
    const float* W_attn = (const float*)d_in[1];
    const float* b_attn = (const float*)d_in[2];
    const float* W_proj = (const float*)d_in[3];
    const float* b_proj = (const float*)d_in[4];
    float* out = (float*)d_out;

    __nv_bfloat16 *xh, *xl, *qhp, *qlp, *khp, *klp, *yhp, *ylp;
    __half *vhp, *vlp;
    __nv_bfloat16 *wah, *wal, *wph, *wpl;
    cudaGetSymbolAddress((void**)&xh,  g_xh);
    cudaGetSymbolAddress((void**)&xl,  g_xl);
    cudaGetSymbolAddress((void**)&qhp, g_qh);
    cudaGetSymbolAddress((void**)&qlp, g_ql);
    cudaGetSymbolAddress((void**)&khp, g_kh);
    cudaGetSymbolAddress((void**)&klp, g_kl);
    cudaGetSymbolAddress((void**)&vhp, g_vh);
    cudaGetSymbolAddress((void**)&vlp, g_vl);
    cudaGetSymbolAddress((void**)&yhp, g_yh);
    cudaGetSymbolAddress((void**)&ylp, g_yl);
    cudaGetSymbolAddress((void**)&wah, g_wah);
    cudaGetSymbolAddress((void**)&wal, g_wal);
    cudaGetSymbolAddress((void**)&wph, g_wph);
    cudaGetSymbolAddress((void**)&wpl, g_wpl);

    cudaFuncSetAttribute(gemm_mma_bf16x3, cudaFuncAttributeMaxDynamicSharedMemorySize,
                         (int)GEMM_SMEM);
    cudaFuncSetAttribute(flash_attn_mma, cudaFuncAttributeMaxDynamicSharedMemorySize,
                         (int)ATT_SMEM);

    prep_fused<<<XB + 4096, 256>>>(x, xh, xl, W_attn, wah, wal, W_proj, wph, wpl);

    gemm_mma_bf16x3<<<dim3(3 * DD / GBN, MROWS / GBM), 256, GEMM_SMEM>>>(
        xh, xl, wah, wal, b_attn, nullptr, 3 * DD, 1,
        qhp, qlp, khp, klp, vhp, vlp);

    flash_attn_mma<<<dim3(SS / 64, HH, BB), 128, ATT_SMEM>>>(
        qhp, qlp, khp, klp, vhp, vlp, yhp, ylp);

    gemm_mma_bf16x3<<<dim3(DD / GBN, MROWS / GBM), 256, GEMM_SMEM>>>(
        yhp, ylp, wph, wpl, b_proj, out, DD, 0,
        nullptr, nullptr, nullptr, nullptr, nullptr, nullptr);
}

// round 17
// speedup vs baseline: 1.1410x; 1.0499x over previous
#include <cuda_runtime.h>
#include <cuda_bf16.h>
#include <cuda_fp16.h>
#include <math.h>
#include <stdint.h>

// Problem shape (fixed by the reference)
#define BB 4
#define SS 2048
#define DD 1024
#define HH 16
#define HDIM 64
#define MROWS (BB * SS)          // 8192
#define KDIM 1024

// ---------------------------------------------------------------------------
// Scratch: device globals (no cudaMalloc allowed)
// ---------------------------------------------------------------------------
__device__ __nv_bfloat16 g_xh[(size_t)MROWS * KDIM];
__device__ __nv_bfloat16 g_xl[(size_t)MROWS * KDIM];
__device__ __nv_bfloat16 g_qh[(size_t)MROWS * DD];
__device__ __nv_bfloat16 g_ql[(size_t)MROWS * DD];
__device__ __nv_bfloat16 g_kh[(size_t)MROWS * DD];
__device__ __nv_bfloat16 g_kl[(size_t)MROWS * DD];
__device__ __half        g_vh[(size_t)MROWS * DD];
__device__ __half        g_vl[(size_t)MROWS * DD];
__device__ __half        g_yh[(size_t)MROWS * KDIM];   // y hi/lo now fp16
__device__ __half        g_yl[(size_t)MROWS * KDIM];
__device__ __nv_bfloat16 g_wah[(size_t)3 * DD * KDIM]; // W_attn^T hi/lo [N,K]
__device__ __nv_bfloat16 g_wal[(size_t)3 * DD * KDIM];
__device__ __half        g_wph[(size_t)DD * KDIM];     // W_proj^T single fp16 [N,K]

// ---------------------------------------------------------------------------
// PTX helpers (base ISA only: cp.async / ldmatrix / mma.sync)
// ---------------------------------------------------------------------------
__device__ __forceinline__ uint32_t smem_u32(const void* p) {
    uint32_t a;
    asm("{ .reg .u64 t; cvta.to.shared.u64 t, %1; cvt.u32.u64 %0, t; }"
        : "=r"(a) : "l"(p));
    return a;
}

#define CP16(smem, gptr) \
    asm volatile("cp.async.cg.shared.global [%0], [%1], 16;" :: "r"(smem), "l"(gptr))
#define CP_COMMIT() asm volatile("cp.async.commit_group;" ::: "memory")
#define CP_WAIT(n)  asm volatile("cp.async.wait_group %0;" :: "n"(n) : "memory")

__device__ __forceinline__ void ldsm4(uint32_t* r, uint32_t addr) {
    asm volatile("ldmatrix.sync.aligned.m8n8.x4.shared.b16 {%0,%1,%2,%3}, [%4];"
                 : "=r"(r[0]), "=r"(r[1]), "=r"(r[2]), "=r"(r[3]) : "r"(addr));
}
__device__ __forceinline__ void ldsm4t(uint32_t* r, uint32_t addr) {
    asm volatile("ldmatrix.sync.aligned.m8n8.x4.trans.shared.b16 {%0,%1,%2,%3}, [%4];"
                 : "=r"(r[0]), "=r"(r[1]), "=r"(r[2]), "=r"(r[3]) : "r"(addr));
}

// bf16 mma
__device__ __forceinline__ void mma16816(float* c, const uint32_t* a, const uint32_t* b) {
    asm volatile(
        "mma.sync.aligned.m16n8k16.row.col.f32.bf16.bf16.f32 "
        "{%0,%1,%2,%3}, {%4,%5,%6,%7}, {%8,%9}, {%0,%1,%2,%3};"
        : "+f"(c[0]), "+f"(c[1]), "+f"(c[2]), "+f"(c[3])
        : "r"(a[0]), "r"(a[1]), "r"(a[2]), "r"(a[3]), "r"(b[0]), "r"(b[1]));
}
// fp16 mma
__device__ __forceinline__ void mma16816h(float* c, const uint32_t* a, const uint32_t* b) {
    asm volatile(
        "mma.sync.aligned.m16n8k16.row.col.f32.f16.f16.f32 "
        "{%0,%1,%2,%3}, {%4,%5,%6,%7}, {%8,%9}, {%0,%1,%2,%3};"
        : "+f"(c[0]), "+f"(c[1]), "+f"(c[2]), "+f"(c[3])
        : "r"(a[0]), "r"(a[1]), "r"(a[2]), "r"(a[3]), "r"(b[0]), "r"(b[1]));
}

__device__ __forceinline__ uint32_t pack_h2(float a, float b) {
    __half2 t = __floats2half2_rn(a, b);
    return *(uint32_t*)&t;
}

// ---------------------------------------------------------------------------
// Fused prep: x hi/lo split (bf16), W_attn^T hi/lo (bf16), W_proj^T (fp16).
// ---------------------------------------------------------------------------
#define XB (MROWS * KDIM / 4 / 256)   // 8192 blocks for x

__global__ __launch_bounds__(256) void prep_fused(
    const float* __restrict__ x, __nv_bfloat16* __restrict__ xh,
    __nv_bfloat16* __restrict__ xl,
    const float* __restrict__ Wa, __nv_bfloat16* __restrict__ bah,
    __nv_bfloat16* __restrict__ bal,
    const float* __restrict__ Wp, __half* __restrict__ bph)
{
    int bz = blockIdx.x;
    if (bz < XB) {
        int i = bz * 256 + threadIdx.x;
        float4 v = ((const float4*)x)[i];
        __nv_bfloat16 h0 = __float2bfloat16(v.x), h1 = __float2bfloat16(v.y);
        __nv_bfloat16 h2 = __float2bfloat16(v.z), h3 = __float2bfloat16(v.w);
        __nv_bfloat162* hp = (__nv_bfloat162*)xh;
        __nv_bfloat162* lp = (__nv_bfloat162*)xl;
        hp[2 * i + 0] = __halves2bfloat162(h0, h1);
        hp[2 * i + 1] = __halves2bfloat162(h2, h3);
        lp[2 * i + 0] = __floats2bfloat162_rn(v.x - __bfloat162float(h0),
                                              v.y - __bfloat162float(h1));
        lp[2 * i + 1] = __floats2bfloat162_rn(v.z - __bfloat162float(h2),
                                              v.w - __bfloat162float(h3));
        return;
    }
    __shared__ float t[32][33];
    int idx = bz - XB;
    int bx = idx & 127;
    int by = idx >> 7;
    int k0 = by * 32;
    int tx = threadIdx.x & 31, ty = threadIdx.x >> 5;
    if (bx < 96) {
        int n0 = bx * 32;
        for (int r = ty; r < 32; r += 8)
            t[r][tx] = Wa[(size_t)(k0 + r) * (3 * DD) + n0 + tx];
        __syncthreads();
        for (int r = ty; r < 32; r += 8) {
            float v = t[tx][r];
            __nv_bfloat16 h = __float2bfloat16(v);
            bah[(size_t)(n0 + r) * KDIM + k0 + tx] = h;
            bal[(size_t)(n0 + r) * KDIM + k0 + tx] =
                __float2bfloat16(v - __bfloat162float(h));
        }
    } else {
        int n0 = (bx - 96) * 32;
        for (int r = ty; r < 32; r += 8)
            t[r][tx] = Wp[(size_t)(k0 + r) * DD + n0 + tx];
        __syncthreads();
        for (int r = ty; r < 32; r += 8)
            bph[(size_t)(n0 + r) * KDIM + k0 + tx] = __float2half_rn(t[tx][r]);
    }
}

// ---------------------------------------------------------------------------
// Shared GEMM tile constants
// ---------------------------------------------------------------------------
#define GBM 128
#define GBN 128
#define GBK 32
#define TILE_BYTES (64 * 128)
#define QSCALE (0.125f * 1.4426950408889634f)

__device__ __forceinline__ uint32_t a_addr(uint32_t tb, int m0, int ks, int lane) {
    int row = m0 + (lane & 15);
    int p = row >> 1;
    int chl = ((row & 1) << 2) | (ks << 1) | (lane >> 4);
    return tb + p * 128 + ((chl ^ (p & 7)) << 4);
}
__device__ __forceinline__ uint32_t b_addr(uint32_t tb, int n0, int ks, int lane) {
    int row = n0 + (lane & 7) + ((lane >> 4) << 3);
    int p = row >> 1;
    int chl = ((row & 1) << 2) | (ks << 1) | ((lane >> 3) & 1);
    return tb + p * 128 + ((chl ^ (p & 7)) << 4);
}

// ---------------------------------------------------------------------------
// GEMM1: bf16x3, qkv projection with split-write epilogue (unchanged logic)
// ---------------------------------------------------------------------------
#define STAGE_BYTES (4 * TILE_BYTES)
#define NSTAGE 3
#define GEMM_SMEM (NSTAGE * STAGE_BYTES)     // 98304

__global__ __launch_bounds__(256, 2) void gemm_mma_bf16x3(
    const __nv_bfloat16* __restrict__ Ah, const __nv_bfloat16* __restrict__ Al,
    const __nv_bfloat16* __restrict__ Bh, const __nv_bfloat16* __restrict__ Bl,
    const float* __restrict__ bias,
    __nv_bfloat16* __restrict__ oqh, __nv_bfloat16* __restrict__ oql,
    __nv_bfloat16* __restrict__ okh, __nv_bfloat16* __restrict__ okl,
    __half* __restrict__ ovh, __half* __restrict__ ovl)
{
    extern __shared__ __align__(1024) char smraw[];
    const uint32_t sbase = smem_u32(smraw);
    const int tid = threadIdx.x;
    const int lane = tid & 31;
    const int wid = tid >> 5;
    const int wm = wid & 1;
    const int wn = wid >> 1;
    const int row0 = blockIdx.y * GBM;
    const int col0 = blockIdx.x * GBN;

    const int frow = tid >> 2;
    const int fkc  = tid & 3;
    uint32_t so0, so1;
    {
        int p0 = frow >> 1;
        int c0 = (((frow & 1) << 2) | fkc) ^ (p0 & 7);
        so0 = (uint32_t)(p0 * 128 + c0 * 16);
        int r1 = frow + 64;
        int p1 = r1 >> 1;
        int c1 = (((r1 & 1) << 2) | fkc) ^ (p1 & 7);
        so1 = (uint32_t)(p1 * 128 + c1 * 16);
    }
    const __nv_bfloat16* fs0 = Ah + (size_t)(row0 + frow) * KDIM + fkc * 8;
    const __nv_bfloat16* fs1 = Al + (size_t)(row0 + frow) * KDIM + fkc * 8;
    const __nv_bfloat16* fs2 = Bh + (size_t)(col0 + frow) * KDIM + fkc * 8;
    const __nv_bfloat16* fs3 = Bl + (size_t)(col0 + frow) * KDIM + fkc * 8;
    const size_t rstep = (size_t)64 * KDIM;

    float acc[4][4][4];
#pragma unroll
    for (int mi = 0; mi < 4; mi++)
#pragma unroll
        for (int ni = 0; ni < 4; ni++)
#pragma unroll
            for (int q = 0; q < 4; q++) acc[mi][ni][q] = 0.0f;

    auto fill = [&](int s) {
        uint32_t stg = sbase + s * STAGE_BYTES;
        CP16(stg + so0, fs0);                  CP16(stg + so1, fs0 + rstep);
        CP16(stg + TILE_BYTES + so0, fs1);     CP16(stg + TILE_BYTES + so1, fs1 + rstep);
        CP16(stg + 2 * TILE_BYTES + so0, fs2); CP16(stg + 2 * TILE_BYTES + so1, fs2 + rstep);
        CP16(stg + 3 * TILE_BYTES + so0, fs3); CP16(stg + 3 * TILE_BYTES + so1, fs3 + rstep);
        fs0 += GBK; fs1 += GBK; fs2 += GBK; fs3 += GBK;
        CP_COMMIT();
    };

    fill(0);
    fill(1);

    const int NCH = KDIM / GBK;   // 32
    for (int c = 0; c < NCH; c++) {
        int s = c % 3;
        if (c + 2 < NCH) { CP_WAIT(1); } else { CP_WAIT(0); }
        __syncthreads();
        if (c + 2 < NCH) fill((c + 2) % 3);

        uint32_t st = sbase + s * STAGE_BYTES;
#pragma unroll
        for (int ks = 0; ks < 2; ks++) {
            uint32_t aH[4][4], aL[4][4];
#pragma unroll
            for (int mi = 0; mi < 4; mi++) {
                ldsm4(aH[mi], a_addr(st,              wm * 64 + mi * 16, ks, lane));
                ldsm4(aL[mi], a_addr(st + TILE_BYTES, wm * 64 + mi * 16, ks, lane));
            }
#pragma unroll
            for (int g = 0; g < 2; g++) {
                uint32_t bh[4], bl[4];
                ldsm4(bh, b_addr(st + 2 * TILE_BYTES, wn * 32 + g * 16, ks, lane));
                ldsm4(bl, b_addr(st + 3 * TILE_BYTES, wn * 32 + g * 16, ks, lane));
#pragma unroll
                for (int mi = 0; mi < 4; mi++) {
                    mma16816(acc[mi][2 * g],     aH[mi], &bh[0]);
                    mma16816(acc[mi][2 * g + 1], aH[mi], &bh[2]);
                }
#pragma unroll
                for (int mi = 0; mi < 4; mi++) {
                    mma16816(acc[mi][2 * g],     aH[mi], &bl[0]);
                    mma16816(acc[mi][2 * g + 1], aH[mi], &bl[2]);
                }
#pragma unroll
                for (int mi = 0; mi < 4; mi++) {
                    mma16816(acc[mi][2 * g],     aL[mi], &bh[0]);
                    mma16816(acc[mi][2 * g + 1], aL[mi], &bh[2]);
                }
            }
        }
    }

    const int qr = lane >> 2, qc = lane & 3;
    int t = col0 >> 10;   // 0=q, 1=k, 2=v
    if (t == 2) {
#pragma unroll
        for (int mi = 0; mi < 4; mi++)
#pragma unroll
            for (int ni = 0; ni < 4; ni++) {
                int row = row0 + wm * 64 + mi * 16 + qr;
                int gcol = col0 + wn * 32 + ni * 8 + qc * 2;
                int lcol = gcol & 1023;
                float2 bv = *(const float2*)(bias + gcol);
                float x0 = acc[mi][ni][0] + bv.x;
                float x1 = acc[mi][ni][1] + bv.y;
                float x2 = acc[mi][ni][2] + bv.x;
                float x3 = acc[mi][ni][3] + bv.y;
                __half h0 = __float2half_rn(x0), h1 = __float2half_rn(x1);
                __half h2 = __float2half_rn(x2), h3 = __float2half_rn(x3);
                size_t i0 = (size_t)row * DD + lcol;
                size_t i1 = (size_t)(row + 8) * DD + lcol;
                *(__half2*)(ovh + i0) = __halves2half2(h0, h1);
                *(__half2*)(ovh + i1) = __halves2half2(h2, h3);
                *(__half2*)(ovl + i0) = __floats2half2_rn(
                    x0 - __half2float(h0), x1 - __half2float(h1));
                *(__half2*)(ovl + i1) = __floats2half2_rn(
                    x2 - __half2float(h2), x3 - __half2float(h3));
            }
    } else {
        __nv_bfloat16* oh = (t == 0) ? oqh : okh;
        __nv_bfloat16* ol = (t == 0) ? oql : okl;
        float sc = (t == 0) ? QSCALE : 1.0f;
#pragma unroll
        for (int mi = 0; mi < 4; mi++)
#pragma unroll
            for (int ni = 0; ni < 4; ni++) {
                int row = row0 + wm * 64 + mi * 16 + qr;
                int gcol = col0 + wn * 32 + ni * 8 + qc * 2;
                int lcol = gcol & 1023;
                float2 bv = *(const float2*)(bias + gcol);
                float x0 = (acc[mi][ni][0] + bv.x) * sc;
                float x1 = (acc[mi][ni][1] + bv.y) * sc;
                float x2 = (acc[mi][ni][2] + bv.x) * sc;
                float x3 = (acc[mi][ni][3] + bv.y) * sc;
                __nv_bfloat16 h0 = __float2bfloat16(x0), h1 = __float2bfloat16(x1);
                __nv_bfloat16 h2 = __float2bfloat16(x2), h3 = __float2bfloat16(x3);
                size_t i0 = (size_t)row * DD + lcol;
                size_t i1 = (size_t)(row + 8) * DD + lcol;
                *(__nv_bfloat162*)(oh + i0) = __halves2bfloat162(h0, h1);
                *(__nv_bfloat162*)(oh + i1) = __halves2bfloat162(h2, h3);
                *(__nv_bfloat162*)(ol + i0) = __floats2bfloat162_rn(
                    x0 - __bfloat162float(h0), x1 - __bfloat162float(h1));
                *(__nv_bfloat162*)(ol + i1) = __floats2bfloat162_rn(
                    x2 - __bfloat162float(h2), x3 - __bfloat162float(h3));
            }
    }
}

// ---------------------------------------------------------------------------
// GEMM2: fp16x2 — C = (Yh + Yl)[M,K] @ Wp[N,K]^T + bias, fp32 out.
// 3 tiles/stage (Ah, Al, Bh), 2 MMA products per fragment.
// ---------------------------------------------------------------------------
#define G2_STAGE (3 * TILE_BYTES)            // 24576
#define G2_SMEM (NSTAGE * G2_STAGE)          // 73728

__global__ __launch_bounds__(256, 2) void gemm_fp16x2(
    const __half* __restrict__ Ah, const __half* __restrict__ Al,
    const __half* __restrict__ Bh,
    const float* __restrict__ bias, float* __restrict__ C)
{
    extern __shared__ __align__(1024) char smraw[];
    const uint32_t sbase = smem_u32(smraw);
    const int tid = threadIdx.x;
    const int lane = tid & 31;
    const int wid = tid >> 5;
    const int wm = wid & 1;
    const int wn = wid >> 1;
    const int row0 = blockIdx.y * GBM;
    const int col0 = blockIdx.x * GBN;

    const int frow = tid >> 2;
    const int fkc  = tid & 3;
    uint32_t so0, so1;
    {
        int p0 = frow >> 1;
        int c0 = (((frow & 1) << 2) | fkc) ^ (p0 & 7);
        so0 = (uint32_t)(p0 * 128 + c0 * 16);
        int r1 = frow + 64;
        int p1 = r1 >> 1;
        int c1 = (((r1 & 1) << 2) | fkc) ^ (p1 & 7);
        so1 = (uint32_t)(p1 * 128 + c1 * 16);
    }
    const __half* fs0 = Ah + (size_t)(row0 + frow) * KDIM + fkc * 8;
    const __half* fs1 = Al + (size_t)(row0 + frow) * KDIM + fkc * 8;
    const __half* fs2 = Bh + (size_t)(col0 + frow) * KDIM + fkc * 8;
    const size_t rstep = (size_t)64 * KDIM;

    float acc[4][4][4];
#pragma unroll
    for (int mi = 0; mi < 4; mi++)
#pragma unroll
        for (int ni = 0; ni < 4; ni++)
#pragma unroll
            for (int q = 0; q < 4; q++) acc[mi][ni][q] = 0.0f;

    auto fill = [&](int s) {
        uint32_t stg = sbase + s * G2_STAGE;
        CP16(stg + so0, fs0);                  CP16(stg + so1, fs0 + rstep);
        CP16(stg + TILE_BYTES + so0, fs1);     CP16(stg + TILE_BYTES + so1, fs1 + rstep);
        CP16(stg + 2 * TILE_BYTES + so0, fs2); CP16(stg + 2 * TILE_BYTES + so1, fs2 + rstep);
        fs0 += GBK; fs1 += GBK; fs2 += GBK;
        CP_COMMIT();
    };

    fill(0);
    fill(1);

    const int NCH = KDIM / GBK;   // 32
    for (int c = 0; c < NCH; c++) {
        int s = c % 3;
        if (c + 2 < NCH) { CP_WAIT(1); } else { CP_WAIT(0); }
        __syncthreads();
        if (c + 2 < NCH) fill((c + 2) % 3);

        uint32_t st = sbase + s * G2_STAGE;
#pragma unroll
        for (int ks = 0; ks < 2; ks++) {
            uint32_t aH[4][4], aL[4][4];
#pragma unroll
            for (int mi = 0; mi < 4; mi++) {
                ldsm4(aH[mi], a_addr(st,              wm * 64 + mi * 16, ks, lane));
                ldsm4(aL[mi], a_addr(st + TILE_BYTES, wm * 64 + mi * 16, ks, lane));
            }
#pragma unroll
            for (int g = 0; g < 2; g++) {
                uint32_t bh[4];
                ldsm4(bh, b_addr(st + 2 * TILE_BYTES, wn * 32 + g * 16, ks, lane));
#pragma unroll
                for (int mi = 0; mi < 4; mi++) {
                    mma16816h(acc[mi][2 * g],     aH[mi], &bh[0]);
                    mma16816h(acc[mi][2 * g + 1], aH[mi], &bh[2]);
                }
#pragma unroll
                for (int mi = 0; mi < 4; mi++) {
                    mma16816h(acc[mi][2 * g],     aL[mi], &bh[0]);
                    mma16816h(acc[mi][2 * g + 1], aL[mi], &bh[2]);
                }
            }
        }
    }

    const int qr = lane >> 2, qc = lane & 3;
#pragma unroll
    for (int mi = 0; mi < 4; mi++)
#pragma unroll
        for (int ni = 0; ni < 4; ni++) {
            int row = row0 + wm * 64 + mi * 16 + qr;
            int col = col0 + wn * 32 + ni * 8 + qc * 2;
            float2 bv = *(const float2*)(bias + col);
            float2 v0, v1;
            v0.x = acc[mi][ni][0] + bv.x;  v0.y = acc[mi][ni][1] + bv.y;
            v1.x = acc[mi][ni][2] + bv.x;  v1.y = acc[mi][ni][3] + bv.y;
            *(float2*)(C + (size_t)row * DD + col) = v0;
            *(float2*)(C + (size_t)(row + 8) * DD + col) = v1;
        }
}

// ---------------------------------------------------------------------------
// Flash attention — R16 structure; epilogue writes y as fp16 hi/lo.
// ---------------------------------------------------------------------------
#define ATT_Q_B 8192                           // 64 rows x 128 B
#define ATT_KV_T 16384                         // 128 rows x 128 B per tensor
#define ATT_SMEM (2 * ATT_Q_B + 4 * ATT_KV_T)  // 81920

__device__ __forceinline__ uint32_t sw128(uint32_t tb, int row, int chunk) {
    return tb + row * 128 + ((chunk ^ (row & 7)) << 4);
}
__device__ __forceinline__ uint32_t fa_a(uint32_t tb, int m0, int ks, int lane) {
    int row = m0 + (lane & 15);
    return sw128(tb, row, ks * 2 + (lane >> 4));
}
__device__ __forceinline__ uint32_t fa_b(uint32_t tb, int n0, int ks, int lane) {
    int row = n0 + (lane & 7) + ((lane >> 4) << 3);
    return sw128(tb, row, ks * 2 + ((lane >> 3) & 1));
}
__device__ __forceinline__ uint32_t fa_v(uint32_t tb, int kv0, int hd0, int lane) {
    int row = kv0 + (((lane >> 3) & 1) << 3) + (lane & 7);
    return sw128(tb, row, (hd0 >> 3) + (lane >> 4));
}

__global__ __launch_bounds__(128, 2) void flash_attn_mma(
    const __nv_bfloat16* __restrict__ qh, const __nv_bfloat16* __restrict__ ql,
    const __nv_bfloat16* __restrict__ kh, const __nv_bfloat16* __restrict__ kl,
    const __half* __restrict__ vh, const __half* __restrict__ vl,
    __half* __restrict__ yh, __half* __restrict__ yl)
{
    extern __shared__ __align__(1024) char smraw[];
    const uint32_t sb = smem_u32(smraw);
    const int qt = (SS / 64 - 1) - blockIdx.x;   // LPT
    const int h = blockIdx.y, b = blockIdx.z;
    const int tid = threadIdx.x, lane = tid & 31, w = tid >> 5;
    const size_t rowbase = (size_t)(b * SS) + qt * 64;
    const int hoff = h * HDIM;

    const uint32_t sQh = sb, sQl = sb + ATT_Q_B;
    const uint32_t tKh = sb + 2 * ATT_Q_B;
    const uint32_t tKl = tKh + ATT_KV_T;
    const uint32_t tVh = tKh + 2 * ATT_KV_T;
    const uint32_t tVl = tKh + 3 * ATT_KV_T;

    {
        const __nv_bfloat16* qs[2] = {qh, ql};
        for (int i = tid; i < 1024; i += 128) {
            int t = i >> 9, idx = i & 511, r = idx >> 3, ch = idx & 7;
            CP16(sw128(t ? sQl : sQh, r, ch),
                 qs[t] + (rowbase + r) * DD + hoff + ch * 8);
        }
        CP_COMMIT();
    }

    const __nv_bfloat16* ks2[2] = {kh, kl};
    const __half* vs2[2] = {vh, vl};
    auto fillK = [&](int kt) {
        size_t kvrow = (size_t)(b * SS) + (size_t)kt * 128;
        for (int i = tid; i < 2048; i += 128) {
            int t = i >> 10, idx = i & 1023, r = idx >> 3, ch = idx & 7;
            CP16(sw128(tKh + t * ATT_KV_T, r, ch),
                 ks2[t] + (kvrow + r) * DD + hoff + ch * 8);
        }
        CP_COMMIT();
    };
    auto fillV = [&](int kt) {
        size_t kvrow = (size_t)(b * SS) + (size_t)kt * 128;
        for (int i = tid; i < 2048; i += 128) {
            int t = i >> 10, idx = i & 1023, r = idx >> 3, ch = idx & 7;
            CP16(sw128(tVh + t * ATT_KV_T, r, ch),
                 vs2[t] + (kvrow + r) * DD + hoff + ch * 8);
        }
        CP_COMMIT();
    };

    float o[8][4];
#pragma unroll
    for (int i = 0; i < 8; i++)
#pragma unroll
        for (int q = 0; q < 4; q++) o[i][q] = 0.0f;
    float mrow[2] = {-1e30f, -1e30f};
    float lrow[2] = {0.0f, 0.0f};

    uint32_t aQh[4][4], aQl[4][4];
    const int qr = lane >> 2, qc = lane & 3;

    const int nkt = (qt + 2) >> 1;

    for (int kt = 0; kt < nkt; kt++) {
        fillK(kt);
        fillV(kt);
        CP_WAIT(1);
        __syncthreads();

        if (kt == 0) {
#pragma unroll
            for (int ks = 0; ks < 4; ks++) {
                ldsm4(aQh[ks], fa_a(sQh, w * 16, ks, lane));
                ldsm4(aQl[ks], fa_a(sQl, w * 16, ks, lane));
            }
        }

        float sfr[16][4];
#pragma unroll
        for (int i = 0; i < 16; i++)
#pragma unroll
            for (int q = 0; q < 4; q++) sfr[i][q] = 0.0f;

#pragma unroll
        for (int ks = 0; ks < 4; ks++)
#pragma unroll
            for (int np = 0; np < 4; np++) {
                int ng0 = 2 * np, ng1 = 2 * np + 1;
                uint32_t bhA[4], blA[4], bhB[4], blB[4];
                ldsm4(bhA, fa_b(tKh, ng0 * 16, ks, lane));
                ldsm4(blA, fa_b(tKl, ng0 * 16, ks, lane));
                ldsm4(bhB, fa_b(tKh, ng1 * 16, ks, lane));
                ldsm4(blB, fa_b(tKl, ng1 * 16, ks, lane));
                mma16816(sfr[2 * ng0],     aQh[ks], &bhA[0]);
                mma16816(sfr[2 * ng0 + 1], aQh[ks], &bhA[2]);
                mma16816(sfr[2 * ng1],     aQh[ks], &bhB[0]);
                mma16816(sfr[2 * ng1 + 1], aQh[ks], &bhB[2]);
                mma16816(sfr[2 * ng0],     aQh[ks], &blA[0]);
                mma16816(sfr[2 * ng0 + 1], aQh[ks], &blA[2]);
                mma16816(sfr[2 * ng1],     aQh[ks], &blB[0]);
                mma16816(sfr[2 * ng1 + 1], aQh[ks], &blB[2]);
                mma16816(sfr[2 * ng0],     aQl[ks], &bhA[0]);
                mma16816(sfr[2 * ng0 + 1], aQl[ks], &bhA[2]);
                mma16816(sfr[2 * ng1],     aQl[ks], &bhB[0]);
                mma16816(sfr[2 * ng1 + 1], aQl[ks], &bhB[2]);
            }

        if (kt == nkt - 1) {
            int r0 = w * 16 + qr;
            int cbase = kt * 128 - qt * 64;
#pragma unroll
            for (int nf = 0; nf < 16; nf++) {
                int c0 = cbase + nf * 8 + qc * 2;
                if (c0 > r0)     sfr[nf][0] = -1e30f;
                if (c0 + 1 > r0) sfr[nf][1] = -1e30f;
                if (c0 > r0 + 8)     sfr[nf][2] = -1e30f;
                if (c0 + 1 > r0 + 8) sfr[nf][3] = -1e30f;
            }
        }

        float tm0 = -1e30f, tm1 = -1e30f;
#pragma unroll
        for (int nf = 0; nf < 16; nf++) {
            tm0 = fmaxf(tm0, fmaxf(sfr[nf][0], sfr[nf][1]));
            tm1 = fmaxf(tm1, fmaxf(sfr[nf][2], sfr[nf][3]));
        }
#pragma unroll
        for (int off = 1; off <= 2; off <<= 1) {
            tm0 = fmaxf(tm0, __shfl_xor_sync(0xffffffffu, tm0, off));
            tm1 = fmaxf(tm1, __shfl_xor_sync(0xffffffffu, tm1, off));
        }
        float mn0 = fmaxf(mrow[0], tm0), mn1 = fmaxf(mrow[1], tm1);
        float al0 = exp2f(mrow[0] - mn0), al1 = exp2f(mrow[1] - mn1);
        mrow[0] = mn0; mrow[1] = mn1;
#pragma unroll
        for (int i = 0; i < 8; i++) {
            o[i][0] *= al0; o[i][1] *= al0;
            o[i][2] *= al1; o[i][3] *= al1;
        }

        float rs0 = 0.0f, rs1 = 0.0f;
#pragma unroll
        for (int nf = 0; nf < 16; nf++) {
            sfr[nf][0] = exp2f(sfr[nf][0] - mn0);
            sfr[nf][1] = exp2f(sfr[nf][1] - mn0);
            sfr[nf][2] = exp2f(sfr[nf][2] - mn1);
            sfr[nf][3] = exp2f(sfr[nf][3] - mn1);
            rs0 += sfr[nf][0] + sfr[nf][1];
            rs1 += sfr[nf][2] + sfr[nf][3];
        }

        CP_WAIT(0);
        __syncthreads();

        // ---- O += P @ V  (P fp16; P*Vh + P*Vl) ----
#pragma unroll
        for (int ks = 0; ks < 8; ks++) {
            const float* f0 = sfr[2 * ks];
            const float* f1 = sfr[2 * ks + 1];
            uint32_t phx[4];
            phx[0] = pack_h2(f0[0], f0[1]);
            phx[1] = pack_h2(f0[2], f0[3]);
            phx[2] = pack_h2(f1[0], f1[1]);
            phx[3] = pack_h2(f1[2], f1[3]);
#pragma unroll
            for (int gp = 0; gp < 2; gp++) {
                int ng0 = 2 * gp, ng1 = 2 * gp + 1;
                uint32_t vhA[4], vlA[4], vhB[4], vlB[4];
                ldsm4t(vhA, fa_v(tVh, ks * 16, ng0 * 16, lane));
                ldsm4t(vlA, fa_v(tVl, ks * 16, ng0 * 16, lane));
                ldsm4t(vhB, fa_v(tVh, ks * 16, ng1 * 16, lane));
                ldsm4t(vlB, fa_v(tVl, ks * 16, ng1 * 16, lane));
                mma16816h(o[2 * ng0],     phx, &vhA[0]);
                mma16816h(o[2 * ng0 + 1], phx, &vhA[2]);
                mma16816h(o[2 * ng1],     phx, &vhB[0]);
                mma16816h(o[2 * ng1 + 1], phx, &vhB[2]);
                mma16816h(o[2 * ng0],     phx, &vlA[0]);
                mma16816h(o[2 * ng0 + 1], phx, &vlA[2]);
                mma16816h(o[2 * ng1],     phx, &vlB[0]);
                mma16816h(o[2 * ng1 + 1], phx, &vlB[2]);
            }
        }

#pragma unroll
        for (int off = 1; off <= 2; off <<= 1) {
            rs0 += __shfl_xor_sync(0xffffffffu, rs0, off);
            rs1 += __shfl_xor_sync(0xffffffffu, rs1, off);
        }
        lrow[0] = lrow[0] * al0 + rs0;
        lrow[1] = lrow[1] * al1 + rs1;

        __syncthreads();
    }

    // ---- epilogue: O/l -> yh/yl (fp16 hi/lo) ----
    float inv0 = 1.0f / lrow[0];
    float inv1 = 1.0f / lrow[1];
    size_t r0 = rowbase + w * 16 + qr;
#pragma unroll
    for (int i = 0; i < 8; i++) {
        int col = hoff + i * 8 + qc * 2;
        float x0 = o[i][0] * inv0, x1 = o[i][1] * inv0;
        float x2 = o[i][2] * inv1, x3 = o[i][3] * inv1;
        __half h0 = __float2half_rn(x0), h1 = __float2half_rn(x1);
        __half h2 = __float2half_rn(x2), h3 = __float2half_rn(x3);
        size_t i0 = r0 * DD + col;
        size_t i1 = (r0 + 8) * DD + col;
        *(__half2*)(yh + i0) = __halves2half2(h0, h1);
        *(__half2*)(yh + i1) = __halves2half2(h2, h3);
        *(__half2*)(yl + i0) = __floats2half2_rn(
            x0 - __half2float(h0), x1 - __half2float(h1));
        *(__half2*)(yl + i1) = __floats2half2_rn(
            x2 - __half2float(h2), x3 - __half2float(h3));
    }
}

// ---------------------------------------------------------------------------
extern "C" void kernel_launch(void* const* d_in, const int* in_sizes, int n_in,
                              void* d_out, int out_size)
{
    const float* x      = (const float*)d_in[0];
    const float* W_attn = (const float*)d_in[1];
    const float* b_attn = (const float*)d_in[2];
    const float* W_proj = (const float*)d_in[3];
    const float* b_proj = (const float*)d_in[4];
    float* out = (float*)d_out;

    __nv_bfloat16 *xh, *xl, *qhp, *qlp, *khp, *klp;
    __half *vhp, *vlp, *yhp, *ylp, *wph;
    __nv_bfloat16 *wah, *wal;
    cudaGetSymbolAddress((void**)&xh,  g_xh);
    cudaGetSymbolAddress((void**)&xl,  g_xl);
    cudaGetSymbolAddress((void**)&qhp, g_qh);
    cudaGetSymbolAddress((void**)&qlp, g_ql);
    cudaGetSymbolAddress((void**)&khp, g_kh);
    cudaGetSymbolAddress((void**)&klp, g_kl);
    cudaGetSymbolAddress((void**)&vhp, g_vh);
    cudaGetSymbolAddress((void**)&vlp, g_vl);
    cudaGetSymbolAddress((void**)&yhp, g_yh);
    cudaGetSymbolAddress((void**)&ylp, g_yl);
    cudaGetSymbolAddress((void**)&wah, g_wah);
    cudaGetSymbolAddress((void**)&wal, g_wal);
    cudaGetSymbolAddress((void**)&wph, g_wph);

    cudaFuncSetAttribute(gemm_mma_bf16x3, cudaFuncAttributeMaxDynamicSharedMemorySize,
                         (int)GEMM_SMEM);
    cudaFuncSetAttribute(gemm_fp16x2, cudaFuncAttributeMaxDynamicSharedMemorySize,
                         (int)G2_SMEM);
    cudaFuncSetAttribute(flash_attn_mma, cudaFuncAttributeMaxDynamicSharedMemorySize,
                         (int)ATT_SMEM);

    prep_fused<<<XB + 4096, 256>>>(x, xh, xl, W_attn, wah, wal, W_proj, wph);

    gemm_mma_bf16x3<<<dim3(3 * DD / GBN, MROWS / GBM), 256, GEMM_SMEM>>>(
        xh, xl, wah, wal, b_attn,
        qhp, qlp, khp, klp, vhp, vlp);

    flash_attn_mma<<<dim3(SS / 64, HH, BB), 128, ATT_SMEM>>>(
        qhp, qlp, khp, klp, vhp, vlp, yhp, ylp);

    gemm_fp16x2<<<dim3(DD / GBN, MROWS / GBM), 256, G2_SMEM>>>(
        yhp, ylp, wph, b_proj, out);
}